// round 3
// baseline (speedup 1.0000x reference)
#include <cuda_runtime.h>
#include <cuda_bf16.h>
#include <math.h>
#include <stdint.h>

// ---------------- problem constants ----------------
#define ROWS 4096        // B*N
#define CDIM 512
#define QKVD 1536
#define HID  2048
#define NHEAD 8
#define HD   64
#define NQ   1024
#define BHN  32768       // B*H*N = 32*1024
#define NBKT 81

// ---------------- device scratch (no allocations allowed) ----------------
__device__ float g_ln    [2][ROWS*CDIM];
__device__ float g_qkv   [2][ROWS*QKVD];
__device__ float g_att   [2][ROWS*CDIM];
__device__ float g_lk    [2][(size_t)BHN*NBKT];
__device__ float g_lq    [2][(size_t)BHN*NBKT];
__device__ float g_logits[2][(size_t)32*NQ*NQ];
__device__ float g_ml    [2][BHN*2];
__device__ float g_hid   [2][(size_t)ROWS*HID];

// piecewise_index(d) for d=-31..31 (ALPHA=1.9, BETA=3.8, GAMMA=15.2)
__constant__ signed char c_pidx[63] = {
  -4,-4,-4,-4,-4,-4,-4,-4,-4,-4,-4,-4,-4,-4,-4,-4,-4,-4,-4,-4,-4,
  -3,-3,-3,-3,-3,-3,-3,
  -2,-2,
  -1,
   0,
   1,
   2, 2,
   3, 3, 3, 3, 3, 3, 3,
   4, 4, 4, 4, 4, 4, 4, 4, 4, 4, 4, 4, 4, 4, 4, 4, 4, 4, 4, 4, 4
};

// ---------------- layernorm: one row (C=512) per block, 128 threads --------
__global__ void ln_kernel(const float* __restrict__ x, const float* __restrict__ gam,
                          const float* __restrict__ bet, float* __restrict__ y)
{
  int row = blockIdx.x;
  int t = threadIdx.x;
  const float* xr = x + (size_t)row * CDIM;
  float4 v = *(const float4*)(xr + t*4);
  float s  = v.x + v.y + v.z + v.w;
  float s2 = v.x*v.x + v.y*v.y + v.z*v.z + v.w*v.w;
  #pragma unroll
  for (int o = 16; o > 0; o >>= 1){
    s  += __shfl_xor_sync(0xffffffffu, s , o);
    s2 += __shfl_xor_sync(0xffffffffu, s2, o);
  }
  __shared__ float rs[4], rq[4];
  if ((t & 31) == 0){ rs[t>>5] = s; rq[t>>5] = s2; }
  __syncthreads();
  s  = rs[0]+rs[1]+rs[2]+rs[3];
  s2 = rq[0]+rq[1]+rq[2]+rq[3];
  float mu   = s  * (1.0f/CDIM);
  float var  = s2 * (1.0f/CDIM) - mu*mu;
  float rstd = rsqrtf(var + 1e-5f);
  float4 g4 = *(const float4*)(gam + t*4);
  float4 b4 = *(const float4*)(bet + t*4);
  float4 o4;
  o4.x = (v.x-mu)*rstd*g4.x + b4.x;
  o4.y = (v.y-mu)*rstd*g4.y + b4.y;
  o4.z = (v.z-mu)*rstd*g4.z + b4.z;
  o4.w = (v.w-mu)*rstd*g4.w + b4.w;
  *(float4*)(y + (size_t)row*CDIM + t*4) = o4;
}

// ---------------- fp32 SGEMM: C = A(MxK)@B(KxN) + bias [gelu] [+resid] ----
__global__ void __launch_bounds__(256, 2) sgemm_kernel(
    const float* __restrict__ A, const float* __restrict__ Bm,
    const float* __restrict__ bias, const float* __restrict__ resid,
    float* __restrict__ C, int M, int N, int K, int gelu)
{
  __shared__ float As[8][128];
  __shared__ float Bs[8][128];
  int t  = threadIdx.x;
  int bn = blockIdx.x * 128;
  int bm = blockIdx.y * 128;
  int tx = t & 15, ty = t >> 4;

  int arow = t >> 1, acol = (t & 1) << 2;
  int brow = t >> 5, bcol = (t & 31) << 2;

  const float* Ag = A  + (size_t)(bm + arow) * K + acol;
  const float* Bg = Bm + (size_t)brow * N + bn + bcol;

  float acc[8][8];
  #pragma unroll
  for (int i = 0; i < 8; i++)
    #pragma unroll
    for (int j = 0; j < 8; j++) acc[i][j] = 0.f;

  float4 av = *(const float4*)Ag;
  float4 bv = *(const float4*)Bg;

  for (int k0 = 0; k0 < K; k0 += 8){
    As[acol+0][arow] = av.x;
    As[acol+1][arow] = av.y;
    As[acol+2][arow] = av.z;
    As[acol+3][arow] = av.w;
    *(float4*)&Bs[brow][bcol] = bv;   // stride 128 floats -> 16B aligned
    __syncthreads();
    if (k0 + 8 < K){
      av = *(const float4*)(Ag + k0 + 8);
      bv = *(const float4*)(Bg + (size_t)(k0 + 8) * N);
    }
    #pragma unroll
    for (int k = 0; k < 8; k++){
      float4 a0 = *(const float4*)&As[k][ty*4];
      float4 a1 = *(const float4*)&As[k][ty*4 + 64];
      float4 b0 = *(const float4*)&Bs[k][tx*4];
      float4 b1 = *(const float4*)&Bs[k][tx*4 + 64];
      float ar[8] = {a0.x,a0.y,a0.z,a0.w,a1.x,a1.y,a1.z,a1.w};
      float br[8] = {b0.x,b0.y,b0.z,b0.w,b1.x,b1.y,b1.z,b1.w};
      #pragma unroll
      for (int i = 0; i < 8; i++)
        #pragma unroll
        for (int j = 0; j < 8; j++) acc[i][j] += ar[i]*br[j];
    }
    __syncthreads();
  }

  float4 bias0 = *(const float4*)(bias + bn + tx*4);
  float4 bias1 = *(const float4*)(bias + bn + tx*4 + 64);
  float bb[8] = {bias0.x,bias0.y,bias0.z,bias0.w,bias1.x,bias1.y,bias1.z,bias1.w};

  #pragma unroll
  for (int i = 0; i < 8; i++){
    int row = bm + (ty<<2) + (i & 3) + ((i >> 2) << 6);
    #pragma unroll
    for (int jh = 0; jh < 2; jh++){
      int col = bn + (tx<<2) + (jh<<6);
      float r0 = acc[i][jh*4+0] + bb[jh*4+0];
      float r1 = acc[i][jh*4+1] + bb[jh*4+1];
      float r2 = acc[i][jh*4+2] + bb[jh*4+2];
      float r3 = acc[i][jh*4+3] + bb[jh*4+3];
      if (gelu){
        r0 = 0.5f*r0*(1.0f + erff(r0*0.70710678f));
        r1 = 0.5f*r1*(1.0f + erff(r1*0.70710678f));
        r2 = 0.5f*r2*(1.0f + erff(r2*0.70710678f));
        r3 = 0.5f*r3*(1.0f + erff(r3*0.70710678f));
      }
      if (resid){
        const float4 rr = *(const float4*)(resid + (size_t)row*N + col);
        r0 += rr.x; r1 += rr.y; r2 += rr.z; r3 += rr.w;
      }
      *(float4*)(C + (size_t)row*N + col) = make_float4(r0,r1,r2,r3);
    }
  }
}

// ---------------- bias tables: LK[i,c]=q_i.tk[c], LQ[j,c]=scale*k_j.tq[c] ---
__global__ void biastab_kernel(const float* __restrict__ qkv0, const float* __restrict__ qkv1,
                               const float* __restrict__ tq, const float* __restrict__ tk)
{
  __shared__ float qrow[3][64];
  int s = blockIdx.z, which = blockIdx.y;
  int rid = blockIdx.x * 3 + threadIdx.y;
  bool ok = (rid < BHN);
  int bh = rid >> 10, n = rid & 1023;
  int b = bh >> 3, h = bh & 7;
  const float* src;
  float scl;
  if (which == 0){ src = (s == 0 ? qkv0 : qkv1);       scl = 1.0f;   }  // Q of stream s
  else           { src = (s == 0 ? qkv1 : qkv0) + 512; scl = 0.125f; }  // K of other stream
  if (ok && threadIdx.x < 64){
    qrow[threadIdx.y][threadIdx.x] =
        scl * src[(size_t)((b<<10)+n)*QKVD + (h<<6) + threadIdx.x];
  }
  __syncthreads();
  if (!ok) return;
  int c = threadIdx.x;  // 0..80
  const float* tab = (which == 0) ? tk : tq;
  const float* tr = tab + c*64;
  float acc = 0.f;
  #pragma unroll
  for (int d = 0; d < 64; d++) acc += qrow[threadIdx.y][d] * tr[d];
  float* dst = (which == 0) ? g_lk[s] : g_lq[s];
  dst[(size_t)rid*NBKT + c] = acc;
}

// ---------------- attention logits: 64x64 tile per block -------------------
__global__ void __launch_bounds__(256) logits_kernel(
    const float* __restrict__ qkv_q, const float* __restrict__ qkv_k,
    const float* __restrict__ LK, const float* __restrict__ LQ,
    float* __restrict__ S)
{
  __shared__ float qs[64][65];
  __shared__ float ks[64][65];
  int t = threadIdx.x;
  int bh = blockIdx.z; int b = bh>>3, h = bh&7;
  int i0 = blockIdx.y<<6, j0 = blockIdx.x<<6;
  const float* qb = qkv_q + (size_t)(b<<10)*QKVD + (h<<6);
  const float* kb = qkv_k + (size_t)(b<<10)*QKVD + (h<<6) + 512;
  #pragma unroll
  for (int it = 0; it < 4; it++){
    int f = t + (it<<8);
    int r = f >> 4, c4 = (f & 15) << 2;
    float4 qv = *(const float4*)(qb + (size_t)(i0+r)*QKVD + c4);
    float4 kv = *(const float4*)(kb + (size_t)(j0+r)*QKVD + c4);
    qs[r][c4+0]=qv.x; qs[r][c4+1]=qv.y; qs[r][c4+2]=qv.z; qs[r][c4+3]=qv.w;
    ks[r][c4+0]=kv.x; ks[r][c4+1]=kv.y; ks[r][c4+2]=kv.z; ks[r][c4+3]=kv.w;
  }
  __syncthreads();
  int tx = t & 15, ty = t >> 4;
  float acc[4][4];
  #pragma unroll
  for (int i=0;i<4;i++)
    #pragma unroll
    for(int j=0;j<4;j++) acc[i][j]=0.f;
  #pragma unroll
  for (int k = 0; k < 64; k++){
    float a[4], bb[4];
    #pragma unroll
    for (int ii=0; ii<4; ii++) a[ii] = qs[(ty<<2)+ii][k];
    #pragma unroll
    for (int jj=0; jj<4; jj++) bb[jj] = ks[(tx<<2)+jj][k];
    #pragma unroll
    for (int ii=0;ii<4;ii++)
      #pragma unroll
      for(int jj=0;jj<4;jj++) acc[ii][jj] += a[ii]*bb[jj];
  }
  size_t rbase = ((size_t)bh)<<10;
  #pragma unroll
  for (int ii=0; ii<4; ii++){
    int i = i0 + (ty<<2) + ii;
    int yi = i >> 5, xi = i & 31;
    const float* lkrow = LK + (rbase + i)*NBKT;
    #pragma unroll
    for (int jj=0; jj<4; jj++){
      int j = j0 + (tx<<2) + jj;
      int dy = yi - (j>>5), dx = xi - (j&31);
      int bkt = ((int)c_pidx[dy+31]+4)*9 + ((int)c_pidx[dx+31]+4);
      float v = acc[ii][jj]*0.125f + lkrow[bkt] + LQ[(rbase + j)*NBKT + 80 - bkt];
      S[(rbase + i)*NQ + j] = v;
    }
  }
}

// ---------------- softmax stats (max, 1/sum) per row of 1024 ---------------
__global__ void smstats_kernel(const float* __restrict__ S, float* __restrict__ ml)
{
  int rid = blockIdx.x;
  int t = threadIdx.x; // 256
  const float4 a = ((const float4*)(S + (size_t)rid*NQ))[t];
  float m = fmaxf(fmaxf(a.x,a.y), fmaxf(a.z,a.w));
  #pragma unroll
  for (int o=16;o>0;o>>=1) m = fmaxf(m, __shfl_xor_sync(0xffffffffu,m,o));
  __shared__ float rm[8], rsum[8];
  if ((t&31)==0) rm[t>>5] = m;
  __syncthreads();
  m = rm[0];
  #pragma unroll
  for (int w=1;w<8;w++) m = fmaxf(m, rm[w]);
  float e = __expf(a.x-m)+__expf(a.y-m)+__expf(a.z-m)+__expf(a.w-m);
  #pragma unroll
  for (int o=16;o>0;o>>=1) e += __shfl_xor_sync(0xffffffffu,e,o);
  if ((t&31)==0) rsum[t>>5] = e;
  __syncthreads();
  if (t==0){
    float s = rsum[0]+rsum[1]+rsum[2]+rsum[3]+rsum[4]+rsum[5]+rsum[6]+rsum[7];
    ml[rid*2]   = m;
    ml[rid*2+1] = 1.0f/s;
  }
}

// ---------------- PV + bucket-scatter + tv epilogue -------------------------
// block: 32 queries x 64 dims. grid (32 i-tiles, 32 bh)
__global__ void __launch_bounds__(256) pv_kernel(
    const float* __restrict__ S, const float* __restrict__ ml,
    const float* __restrict__ qkv_v, const float* __restrict__ tv,
    float* __restrict__ out)
{
  __shared__ float ps[32][65];
  __shared__ float vs[64][65];
  __shared__ float sb[32][NBKT];
  __shared__ float mrow[32], irow[32];
  int t = threadIdx.x;
  int bh = blockIdx.y; int b = bh>>3, h = bh&7;
  int i0 = blockIdx.x << 5;
  size_t rbase = (((size_t)bh)<<10) + i0;
  if (t < 32){ mrow[t] = ml[(rbase+t)*2]; irow[t] = ml[(rbase+t)*2+1]; }
  for (int f = t; f < 32*NBKT; f += 256) (&sb[0][0])[f] = 0.f;
  __syncthreads();
  int tx = t & 15, ty = t >> 4;
  float acc[2][4];
  #pragma unroll
  for (int i=0;i<2;i++)
    #pragma unroll
    for(int d=0;d<4;d++) acc[i][d]=0.f;
  const float* vb = qkv_v + ((size_t)(b<<10))*QKVD + (h<<6) + 1024;

  int sr = t >> 3;              // scatter row 0..31
  int iglob = i0 + sr;
  int syi = iglob >> 5, sxi = iglob & 31;

  for (int jt = 0; jt < 16; jt++){
    int j0 = jt << 6;
    #pragma unroll
    for (int it = 0; it < 2; it++){
      int f = t + (it<<8);
      int r = f >> 4, c4 = (f&15)<<2;
      float4 sv = *(const float4*)(S + (rbase + r)*NQ + j0 + c4);
      float m = mrow[r], inv = irow[r];
      ps[r][c4+0] = __expf(sv.x - m)*inv;
      ps[r][c4+1] = __expf(sv.y - m)*inv;
      ps[r][c4+2] = __expf(sv.z - m)*inv;
      ps[r][c4+3] = __expf(sv.w - m)*inv;
    }
    #pragma unroll
    for (int it = 0; it < 4; it++){
      int f = t + (it<<8);
      int r = f>>4, c4 = (f&15)<<2;
      float4 vv = *(const float4*)(vb + (size_t)(j0+r)*QKVD + c4);
      vs[r][c4+0]=vv.x; vs[r][c4+1]=vv.y; vs[r][c4+2]=vv.z; vs[r][c4+3]=vv.w;
    }
    __syncthreads();
    // bucket scatter: each thread handles 8 j's of one row
    #pragma unroll
    for (int q = 0; q < 8; q++){
      int jj = ((t&7)<<3) + q;
      int j = j0 + jj;
      int dy = syi - (j>>5), dx = sxi - (j&31);
      int bkt = ((int)c_pidx[dy+31]+4)*9 + ((int)c_pidx[dx+31]+4);
      atomicAdd(&sb[sr][bkt], ps[sr][jj]);
    }
    // p @ v
    #pragma unroll
    for (int k = 0; k < 64; k++){
      float bv[4];
      #pragma unroll
      for (int dd=0; dd<4; dd++) bv[dd] = vs[k][(tx<<2)+dd];
      #pragma unroll
      for (int ii=0; ii<2; ii++){
        float a = ps[(ty<<1)+ii][k];
        #pragma unroll
        for (int dd=0;dd<4;dd++) acc[ii][dd] += a*bv[dd];
      }
    }
    __syncthreads();
  }
  // tv term: SB @ table_v
  #pragma unroll
  for (int ii=0; ii<2; ii++){
    int r = (ty<<1)+ii;
    float o0=acc[ii][0], o1=acc[ii][1], o2=acc[ii][2], o3=acc[ii][3];
    for (int c = 0; c < NBKT; c++){
      float sv = sb[r][c];
      const float4 tvv = *(const float4*)(tv + (c<<6) + (tx<<2));
      o0 += sv*tvv.x; o1 += sv*tvv.y; o2 += sv*tvv.z; o3 += sv*tvv.w;
    }
    float* op = out + ((size_t)(b<<10) + i0 + r)*CDIM + (h<<6) + (tx<<2);
    *(float4*)op = make_float4(o0,o1,o2,o3);
  }
}

// ---------------- launch ----------------------------------------------------
extern "C" void kernel_launch(void* const* d_in, const int* in_sizes, int n_in,
                              void* d_out, int out_size)
{
  const float* x0     = (const float*)d_in[0];
  const float* x1     = (const float*)d_in[1];
  const float* ln00_g = (const float*)d_in[2];
  const float* ln00_b = (const float*)d_in[3];
  const float* ln01_g = (const float*)d_in[4];
  const float* ln01_b = (const float*)d_in[5];
  const float* ln10_g = (const float*)d_in[6];
  const float* ln10_b = (const float*)d_in[7];
  const float* ln11_g = (const float*)d_in[8];
  const float* ln11_b = (const float*)d_in[9];
  const float* w_qkv0 = (const float*)d_in[10];
  const float* b_qkv0 = (const float*)d_in[11];
  const float* w_qkv1 = (const float*)d_in[12];
  const float* b_qkv1 = (const float*)d_in[13];
  const float* w_proj = (const float*)d_in[14];
  const float* b_proj = (const float*)d_in[15];
  const float* table_q= (const float*)d_in[16];
  const float* table_k= (const float*)d_in[17];
  const float* table_v= (const float*)d_in[18];
  const float* w_fc1_0= (const float*)d_in[19];
  const float* b_fc1_0= (const float*)d_in[20];
  const float* w_fc2_0= (const float*)d_in[21];
  const float* b_fc2_0= (const float*)d_in[22];
  const float* w_fc1_1= (const float*)d_in[23];
  const float* b_fc1_1= (const float*)d_in[24];
  const float* w_fc2_1= (const float*)d_in[25];
  const float* b_fc2_1= (const float*)d_in[26];

  float* out0 = (float*)d_out;
  float* out1 = (float*)d_out + (size_t)ROWS*CDIM;

  float *ln0, *ln1, *qkv0, *qkv1, *att0, *att1, *lk0, *lk1, *lq0, *lq1;
  float *lg0, *lg1, *ml0, *ml1, *hid0, *hid1;
  cudaGetSymbolAddress((void**)&ln0,  g_ln);     ln1  = ln0  + (size_t)ROWS*CDIM;
  cudaGetSymbolAddress((void**)&qkv0, g_qkv);    qkv1 = qkv0 + (size_t)ROWS*QKVD;
  cudaGetSymbolAddress((void**)&att0, g_att);    att1 = att0 + (size_t)ROWS*CDIM;
  cudaGetSymbolAddress((void**)&lk0,  g_lk);     lk1  = lk0  + (size_t)BHN*NBKT;
  cudaGetSymbolAddress((void**)&lq0,  g_lq);     lq1  = lq0  + (size_t)BHN*NBKT;
  cudaGetSymbolAddress((void**)&lg0,  g_logits); lg1  = lg0  + (size_t)32*NQ*NQ;
  cudaGetSymbolAddress((void**)&ml0,  g_ml);     ml1  = ml0  + (size_t)BHN*2;
  cudaGetSymbolAddress((void**)&hid0, g_hid);    hid1 = hid0 + (size_t)ROWS*HID;

  // 1. LN for qkv inputs
  ln_kernel<<<ROWS, 128>>>(x0, ln00_g, ln00_b, ln0);
  ln_kernel<<<ROWS, 128>>>(x1, ln01_g, ln01_b, ln1);

  // 2. qkv GEMMs
  dim3 gqkv(QKVD/128, ROWS/128);
  sgemm_kernel<<<gqkv, 256>>>(ln0, w_qkv0, b_qkv0, nullptr, qkv0, ROWS, QKVD, CDIM, 0);
  sgemm_kernel<<<gqkv, 256>>>(ln1, w_qkv1, b_qkv1, nullptr, qkv1, ROWS, QKVD, CDIM, 0);

  // 3. bias tables LK/LQ
  dim3 gbt((BHN + 2)/3, 2, 2);
  biastab_kernel<<<gbt, dim3(81,3)>>>(qkv0, qkv1, table_q, table_k);

  // 4. logits (stream 0: q0 x k1 ; stream 1: q1 x k0)
  dim3 glg(16, 16, 32);
  logits_kernel<<<glg, 256>>>(qkv0, qkv1, lk0, lq0, lg0);
  logits_kernel<<<glg, 256>>>(qkv1, qkv0, lk1, lq1, lg1);

  // 5. softmax stats
  smstats_kernel<<<BHN, 256>>>(lg0, ml0);
  smstats_kernel<<<BHN, 256>>>(lg1, ml1);

  // 6. PV + relative-position V table
  dim3 gpv(32, 32);
  pv_kernel<<<gpv, 256>>>(lg0, ml0, qkv1, table_v, att0);
  pv_kernel<<<gpv, 256>>>(lg1, ml1, qkv0, table_v, att1);

  // 7. proj + residual -> out
  dim3 gproj(CDIM/128, ROWS/128);
  sgemm_kernel<<<gproj, 256>>>(att0, w_proj, b_proj, x0, out0, ROWS, CDIM, CDIM, 0);
  sgemm_kernel<<<gproj, 256>>>(att1, w_proj, b_proj, x1, out1, ROWS, CDIM, CDIM, 0);

  // 8. MLP: LN -> fc1(gelu) -> fc2(+resid)
  ln_kernel<<<ROWS, 128>>>(out0, ln10_g, ln10_b, ln0);
  ln_kernel<<<ROWS, 128>>>(out1, ln11_g, ln11_b, ln1);

  dim3 gfc1(HID/128, ROWS/128);
  sgemm_kernel<<<gfc1, 256>>>(ln0, w_fc1_0, b_fc1_0, nullptr, hid0, ROWS, HID, CDIM, 1);
  sgemm_kernel<<<gfc1, 256>>>(ln1, w_fc1_1, b_fc1_1, nullptr, hid1, ROWS, HID, CDIM, 1);

  dim3 gfc2(CDIM/128, ROWS/128);
  sgemm_kernel<<<gfc2, 256>>>(hid0, w_fc2_0, b_fc2_0, out0, out0, ROWS, CDIM, HID, 0);
  sgemm_kernel<<<gfc2, 256>>>(hid1, w_fc2_1, b_fc2_1, out1, out1, ROWS, CDIM, HID, 0);
}

// round 4
// speedup vs baseline: 1.0262x; 1.0262x over previous
#include <cuda_runtime.h>
#include <cuda_bf16.h>
#include <math.h>
#include <stdint.h>

// ---------------- problem constants ----------------
#define ROWS 4096        // B*N
#define CDIM 512
#define QKVD 1536
#define HID  2048
#define NHEAD 8
#define HD   64
#define NQ   1024
#define BHN  32768       // B*H*N = 32*1024
#define NBKT 81

// ---------------- device scratch (no allocations allowed) ----------------
__device__ float g_ln    [2][ROWS*CDIM];
__device__ float g_qkv   [2][ROWS*QKVD];
__device__ float g_att   [2][ROWS*CDIM];
__device__ float g_lk    [2][(size_t)BHN*NBKT];
__device__ float g_lq    [2][(size_t)BHN*NBKT];
__device__ float g_logits[2][(size_t)32*NQ*NQ];
__device__ float g_ml    [2][BHN];
__device__ float g_hid   [2][(size_t)ROWS*HID];

// piecewise_index(d) for d=-31..31 (ALPHA=1.9, BETA=3.8, GAMMA=15.2)
__constant__ signed char c_pidx[63] = {
  -4,-4,-4,-4,-4,-4,-4,-4,-4,-4,-4,-4,-4,-4,-4,-4,-4,-4,-4,-4,-4,
  -3,-3,-3,-3,-3,-3,-3,
  -2,-2,
  -1,
   0,
   1,
   2, 2,
   3, 3, 3, 3, 3, 3, 3,
   4, 4, 4, 4, 4, 4, 4, 4, 4, 4, 4, 4, 4, 4, 4, 4, 4, 4, 4, 4, 4
};

// fast exp on FMA pipe (input <= 0 after max subtraction; |x| < 40 here)
__device__ __forceinline__ float fexp(float x){
  float y = x * 1.4426950408889634f;
  float n = rintf(y);
  float f = y - n;
  float p =           1.3333558e-3f;
  p = fmaf(p, f, 9.6181291e-3f);
  p = fmaf(p, f, 5.5504108e-2f);
  p = fmaf(p, f, 2.4022650e-1f);
  p = fmaf(p, f, 6.9314718e-1f);
  p = fmaf(p, f, 1.0f);
  int ni = (int)n;
  return p * __int_as_float((ni + 127) << 23);
}

// ---------------- layernorm ------------------------------------------------
__global__ void ln_kernel(const float* __restrict__ x, const float* __restrict__ gam,
                          const float* __restrict__ bet, float* __restrict__ y)
{
  int row = blockIdx.x;
  int t = threadIdx.x;
  const float* xr = x + (size_t)row * CDIM;
  float4 v = *(const float4*)(xr + t*4);
  float s  = v.x + v.y + v.z + v.w;
  float s2 = v.x*v.x + v.y*v.y + v.z*v.z + v.w*v.w;
  #pragma unroll
  for (int o = 16; o > 0; o >>= 1){
    s  += __shfl_xor_sync(0xffffffffu, s , o);
    s2 += __shfl_xor_sync(0xffffffffu, s2, o);
  }
  __shared__ float rs[4], rq[4];
  if ((t & 31) == 0){ rs[t>>5] = s; rq[t>>5] = s2; }
  __syncthreads();
  s  = rs[0]+rs[1]+rs[2]+rs[3];
  s2 = rq[0]+rq[1]+rq[2]+rq[3];
  float mu   = s  * (1.0f/CDIM);
  float var  = s2 * (1.0f/CDIM) - mu*mu;
  float rstd = rsqrtf(var + 1e-5f);
  float4 g4 = *(const float4*)(gam + t*4);
  float4 b4 = *(const float4*)(bet + t*4);
  float4 o4;
  o4.x = (v.x-mu)*rstd*g4.x + b4.x;
  o4.y = (v.y-mu)*rstd*g4.y + b4.y;
  o4.z = (v.z-mu)*rstd*g4.z + b4.z;
  o4.w = (v.w-mu)*rstd*g4.w + b4.w;
  *(float4*)(y + (size_t)row*CDIM + t*4) = o4;
}

// ---------------- fp32 SGEMM: C = A(MxK)@B(KxN) + bias [gelu] [+resid] ----
__global__ void __launch_bounds__(256, 2) sgemm_kernel(
    const float* __restrict__ A, const float* __restrict__ Bm,
    const float* __restrict__ bias, const float* __restrict__ resid,
    float* __restrict__ C, int M, int N, int K, int gelu)
{
  __shared__ float As[8][128];
  __shared__ float Bs[8][128];
  int t  = threadIdx.x;
  int bn = blockIdx.x * 128;
  int bm = blockIdx.y * 128;
  int tx = t & 15, ty = t >> 4;

  int arow = t >> 1, acol = (t & 1) << 2;
  int brow = t >> 5, bcol = (t & 31) << 2;

  const float* Ag = A  + (size_t)(bm + arow) * K + acol;
  const float* Bg = Bm + (size_t)brow * N + bn + bcol;

  float acc[8][8];
  #pragma unroll
  for (int i = 0; i < 8; i++)
    #pragma unroll
    for (int j = 0; j < 8; j++) acc[i][j] = 0.f;

  float4 av = *(const float4*)Ag;
  float4 bv = *(const float4*)Bg;

  for (int k0 = 0; k0 < K; k0 += 8){
    As[acol+0][arow] = av.x;
    As[acol+1][arow] = av.y;
    As[acol+2][arow] = av.z;
    As[acol+3][arow] = av.w;
    *(float4*)&Bs[brow][bcol] = bv;
    __syncthreads();
    if (k0 + 8 < K){
      av = *(const float4*)(Ag + k0 + 8);
      bv = *(const float4*)(Bg + (size_t)(k0 + 8) * N);
    }
    #pragma unroll
    for (int k = 0; k < 8; k++){
      float4 a0 = *(const float4*)&As[k][ty*4];
      float4 a1 = *(const float4*)&As[k][ty*4 + 64];
      float4 b0 = *(const float4*)&Bs[k][tx*4];
      float4 b1 = *(const float4*)&Bs[k][tx*4 + 64];
      float ar[8] = {a0.x,a0.y,a0.z,a0.w,a1.x,a1.y,a1.z,a1.w};
      float br[8] = {b0.x,b0.y,b0.z,b0.w,b1.x,b1.y,b1.z,b1.w};
      #pragma unroll
      for (int i = 0; i < 8; i++)
        #pragma unroll
        for (int j = 0; j < 8; j++) acc[i][j] += ar[i]*br[j];
    }
    __syncthreads();
  }

  float4 bias0 = *(const float4*)(bias + bn + tx*4);
  float4 bias1 = *(const float4*)(bias + bn + tx*4 + 64);
  float bb[8] = {bias0.x,bias0.y,bias0.z,bias0.w,bias1.x,bias1.y,bias1.z,bias1.w};

  #pragma unroll
  for (int i = 0; i < 8; i++){
    int row = bm + (ty<<2) + (i & 3) + ((i >> 2) << 6);
    #pragma unroll
    for (int jh = 0; jh < 2; jh++){
      int col = bn + (tx<<2) + (jh<<6);
      float r0 = acc[i][jh*4+0] + bb[jh*4+0];
      float r1 = acc[i][jh*4+1] + bb[jh*4+1];
      float r2 = acc[i][jh*4+2] + bb[jh*4+2];
      float r3 = acc[i][jh*4+3] + bb[jh*4+3];
      if (gelu){
        r0 = 0.5f*r0*(1.0f + erff(r0*0.70710678f));
        r1 = 0.5f*r1*(1.0f + erff(r1*0.70710678f));
        r2 = 0.5f*r2*(1.0f + erff(r2*0.70710678f));
        r3 = 0.5f*r3*(1.0f + erff(r3*0.70710678f));
      }
      if (resid){
        const float4 rr = *(const float4*)(resid + (size_t)row*N + col);
        r0 += rr.x; r1 += rr.y; r2 += rr.z; r3 += rr.w;
      }
      *(float4*)(C + (size_t)row*N + col) = make_float4(r0,r1,r2,r3);
    }
  }
}

// ---------------- bias tables: LK[i,c]=q_i.tk[c], LQ[j,c]=scale*k_j.tq[c] ---
__global__ void biastab_kernel(const float* __restrict__ qkv0, const float* __restrict__ qkv1,
                               const float* __restrict__ tq, const float* __restrict__ tk)
{
  __shared__ float qrow[3][64];
  int s = blockIdx.z, which = blockIdx.y;
  int rid = blockIdx.x * 3 + threadIdx.y;
  bool ok = (rid < BHN);
  int bh = rid >> 10, n = rid & 1023;
  int b = bh >> 3, h = bh & 7;
  const float* src;
  float scl;
  if (which == 0){ src = (s == 0 ? qkv0 : qkv1);       scl = 1.0f;   }
  else           { src = (s == 0 ? qkv1 : qkv0) + 512; scl = 0.125f; }
  if (ok && threadIdx.x < 64){
    qrow[threadIdx.y][threadIdx.x] =
        scl * src[(size_t)((b<<10)+n)*QKVD + (h<<6) + threadIdx.x];
  }
  __syncthreads();
  if (!ok) return;
  int c = threadIdx.x;  // 0..80
  const float* tab = (which == 0) ? tk : tq;
  const float* tr = tab + c*64;
  float acc = 0.f;
  #pragma unroll
  for (int d = 0; d < 64; d++) acc += qrow[threadIdx.y][d] * tr[d];
  float* dst = (which == 0) ? g_lk[s] : g_lq[s];
  dst[(size_t)rid*NBKT + c] = acc;
}

// ---------------- attention logits: 64x64 tile, smem-staged bias tables ----
// dynamic smem: qs[64*65] ks[64*65] lks[64*81] lqs[64*81]
__global__ void __launch_bounds__(256) logits_kernel(
    const float* __restrict__ qkv_q, const float* __restrict__ qkv_k,
    const float* __restrict__ LK, const float* __restrict__ LQ,
    float* __restrict__ S)
{
  extern __shared__ float sm[];
  float* qs  = sm;           // [64][65]
  float* ks  = sm + 4160;    // [64][65]
  float* lks = sm + 8320;    // [64][81]
  float* lqs = sm + 13504;   // [64][81]

  int t = threadIdx.x;
  int bh = blockIdx.z; int b = bh>>3, h = bh&7;
  int i0 = blockIdx.y<<6, j0 = blockIdx.x<<6;
  size_t rbase = ((size_t)bh)<<10;
  const float* qb = qkv_q + (size_t)(b<<10)*QKVD + (h<<6);
  const float* kb = qkv_k + (size_t)(b<<10)*QKVD + (h<<6) + 512;
  #pragma unroll
  for (int it = 0; it < 4; it++){
    int f = t + (it<<8);
    int r = f >> 4, c4 = (f & 15) << 2;
    float4 qv = *(const float4*)(qb + (size_t)(i0+r)*QKVD + c4);
    float4 kv = *(const float4*)(kb + (size_t)(j0+r)*QKVD + c4);
    qs[r*65+c4+0]=qv.x; qs[r*65+c4+1]=qv.y; qs[r*65+c4+2]=qv.z; qs[r*65+c4+3]=qv.w;
    ks[r*65+c4+0]=kv.x; ks[r*65+c4+1]=kv.y; ks[r*65+c4+2]=kv.z; ks[r*65+c4+3]=kv.w;
  }
  // stage LK rows (i-tile) and LQ rows (j-tile)
  for (int f = t; f < 64*NBKT; f += 256){
    int r = f / NBKT, c = f - r*NBKT;
    lks[f] = LK[(rbase + i0 + r)*NBKT + c];
    lqs[f] = LQ[(rbase + j0 + r)*NBKT + c];
  }
  __syncthreads();

  int tx = t & 15, ty = t >> 4;
  float acc[4][4];
  #pragma unroll
  for (int i=0;i<4;i++)
    #pragma unroll
    for(int j=0;j<4;j++) acc[i][j]=0.f;
  #pragma unroll
  for (int k = 0; k < 64; k++){
    float a[4], bb[4];
    #pragma unroll
    for (int ii=0; ii<4; ii++) a[ii] = qs[((ty<<2)+ii)*65 + k];
    #pragma unroll
    for (int jj=0; jj<4; jj++) bb[jj] = ks[((tx<<2)+jj)*65 + k];
    #pragma unroll
    for (int ii=0;ii<4;ii++)
      #pragma unroll
      for(int jj=0;jj<4;jj++) acc[ii][jj] += a[ii]*bb[jj];
  }
  #pragma unroll
  for (int ii=0; ii<4; ii++){
    int il = (ty<<2)+ii;
    int i = i0 + il;
    int yi = i >> 5, xi = i & 31;
    #pragma unroll
    for (int jj=0; jj<4; jj++){
      int jl = (tx<<2)+jj;
      int j = j0 + jl;
      int dy = yi - (j>>5), dx = xi - (j&31);
      int bkt = ((int)c_pidx[dy+31]+4)*9 + ((int)c_pidx[dx+31]+4);
      float v = acc[ii][jj]*0.125f + lks[il*NBKT + bkt] + lqs[jl*NBKT + 80 - bkt];
      S[(rbase + i)*NQ + j] = v;
    }
  }
}

// ---------------- row max only ---------------------------------------------
__global__ void smax_kernel(const float* __restrict__ S, float* __restrict__ ml)
{
  int rid = blockIdx.x;
  int t = threadIdx.x; // 256
  const float4 a = ((const float4*)(S + (size_t)rid*NQ))[t];
  float m = fmaxf(fmaxf(a.x,a.y), fmaxf(a.z,a.w));
  #pragma unroll
  for (int o=16;o>0;o>>=1) m = fmaxf(m, __shfl_xor_sync(0xffffffffu,m,o));
  __shared__ float rm[8];
  if ((t&31)==0) rm[t>>5] = m;
  __syncthreads();
  if (t==0){
    m = rm[0];
    #pragma unroll
    for (int w=1;w<8;w++) m = fmaxf(m, rm[w]);
    ml[rid] = m;
  }
}

// ---------------- PV: 64x64 tile GEMM + run-length bucket scatter ----------
// dynamic smem: ps[64*65] vs[64*65] sb[64*81] tvs[81*64] mrow[64] rsv[64]
__global__ void __launch_bounds__(256) pv_kernel(
    const float* __restrict__ S, const float* __restrict__ ml,
    const float* __restrict__ qkv_v, const float* __restrict__ tv,
    float* __restrict__ out)
{
  extern __shared__ float sm[];
  float* ps  = sm;            // [64][65]  exp(S - m), unnormalized
  float* vs  = sm + 4160;     // [64][65]
  float* sb  = sm + 8320;     // [64][81]
  float* tvs = sm + 13504;    // [81][64]
  float* mrow= sm + 18688;    // [64]
  float* rsv = sm + 18752;    // [64]

  int t = threadIdx.x;
  int bh = blockIdx.y; int b = bh>>3, h = bh&7;
  int i0 = blockIdx.x << 6;
  size_t rb2 = (((size_t)bh)<<10) + i0;
  if (t < 64) mrow[t] = ml[rb2 + t];
  for (int f = t; f < 64*NBKT; f += 256) sb[f] = 0.f;
  for (int f = t; f < NBKT*64; f += 256) tvs[f] = tv[f];
  __syncthreads();

  int tx = t & 15, ty = t >> 4;
  float acc[4][4];
  #pragma unroll
  for (int i=0;i<4;i++)
    #pragma unroll
    for(int d=0;d<4;d++) acc[i][d]=0.f;
  const float* vb = qkv_v + ((size_t)(b<<10))*QKVD + (h<<6) + 1024;

  // scatter mapping: 4 threads per row, 16 consecutive j each
  int sr = t >> 2;
  int q0 = (t & 3) << 4;
  int iglob = i0 + sr;
  int syi = iglob >> 5, sxi = iglob & 31;

  for (int jt = 0; jt < 16; jt++){
    int j0 = jt << 6;
    #pragma unroll
    for (int it = 0; it < 4; it++){
      int f = t + (it<<8);
      int r = f >> 4, c4 = (f&15)<<2;
      float4 sv = *(const float4*)(S + (rb2 + r)*NQ + j0 + c4);
      float m = mrow[r];
      ps[r*65+c4+0] = fexp(sv.x - m);
      ps[r*65+c4+1] = fexp(sv.y - m);
      ps[r*65+c4+2] = fexp(sv.z - m);
      ps[r*65+c4+3] = fexp(sv.w - m);
      float4 vv = *(const float4*)(vb + (size_t)(j0+r)*QKVD + c4);
      vs[r*65+c4+0]=vv.x; vs[r*65+c4+1]=vv.y; vs[r*65+c4+2]=vv.z; vs[r*65+c4+3]=vv.w;
    }
    __syncthreads();

    // run-length aggregated bucket scatter (16 consecutive j per thread)
    {
      float runv = 0.f; int runb = -1;
      #pragma unroll
      for (int q = 0; q < 16; q++){
        int jj = q0 + q;
        int j = j0 + jj;
        int dy = syi - (j>>5), dx = sxi - (j&31);
        int bkt = ((int)c_pidx[dy+31]+4)*9 + ((int)c_pidx[dx+31]+4);
        float pvv = ps[sr*65 + jj];
        if (bkt == runb) runv += pvv;
        else {
          if (runb >= 0) atomicAdd(&sb[sr*NBKT + runb], runv);
          runb = bkt; runv = pvv;
        }
      }
      atomicAdd(&sb[sr*NBKT + runb], runv);
    }

    // p @ v   (64-deep k over this j-tile)
    #pragma unroll
    for (int k = 0; k < 64; k++){
      float bv[4], a[4];
      #pragma unroll
      for (int dd=0; dd<4; dd++) bv[dd] = vs[k*65 + (tx<<2)+dd];
      #pragma unroll
      for (int ii=0; ii<4; ii++) a[ii] = ps[((ty<<2)+ii)*65 + k];
      #pragma unroll
      for (int ii=0;ii<4;ii++)
        #pragma unroll
        for (int dd=0;dd<4;dd++) acc[ii][dd] += a[ii]*bv[dd];
    }
    __syncthreads();
  }

  // row sums = sum of buckets (free normalization)
  if (t < 64){
    float s = 0.f;
    #pragma unroll
    for (int c = 0; c < NBKT; c++) s += sb[t*NBKT + c];
    rsv[t] = 1.0f / s;
  }
  __syncthreads();

  // epilogue: normalize + tv table term
  #pragma unroll
  for (int ii=0; ii<4; ii++){
    int r = (ty<<2)+ii;
    float inv = rsv[r];
    float o0=acc[ii][0]*inv, o1=acc[ii][1]*inv, o2=acc[ii][2]*inv, o3=acc[ii][3]*inv;
    for (int c = 0; c < NBKT; c++){
      float svc = sb[r*NBKT + c] * inv;
      float4 tvv = *(const float4*)&tvs[(c<<6) + (tx<<2)];
      o0 = fmaf(svc, tvv.x, o0); o1 = fmaf(svc, tvv.y, o1);
      o2 = fmaf(svc, tvv.z, o2); o3 = fmaf(svc, tvv.w, o3);
    }
    float* op = out + ((size_t)(b<<10) + i0 + r)*CDIM + (h<<6) + (tx<<2);
    *(float4*)op = make_float4(o0,o1,o2,o3);
  }
}

// ---------------- launch ----------------------------------------------------
extern "C" void kernel_launch(void* const* d_in, const int* in_sizes, int n_in,
                              void* d_out, int out_size)
{
  const float* x0     = (const float*)d_in[0];
  const float* x1     = (const float*)d_in[1];
  const float* ln00_g = (const float*)d_in[2];
  const float* ln00_b = (const float*)d_in[3];
  const float* ln01_g = (const float*)d_in[4];
  const float* ln01_b = (const float*)d_in[5];
  const float* ln10_g = (const float*)d_in[6];
  const float* ln10_b = (const float*)d_in[7];
  const float* ln11_g = (const float*)d_in[8];
  const float* ln11_b = (const float*)d_in[9];
  const float* w_qkv0 = (const float*)d_in[10];
  const float* b_qkv0 = (const float*)d_in[11];
  const float* w_qkv1 = (const float*)d_in[12];
  const float* b_qkv1 = (const float*)d_in[13];
  const float* w_proj = (const float*)d_in[14];
  const float* b_proj = (const float*)d_in[15];
  const float* table_q= (const float*)d_in[16];
  const float* table_k= (const float*)d_in[17];
  const float* table_v= (const float*)d_in[18];
  const float* w_fc1_0= (const float*)d_in[19];
  const float* b_fc1_0= (const float*)d_in[20];
  const float* w_fc2_0= (const float*)d_in[21];
  const float* b_fc2_0= (const float*)d_in[22];
  const float* w_fc1_1= (const float*)d_in[23];
  const float* b_fc1_1= (const float*)d_in[24];
  const float* w_fc2_1= (const float*)d_in[25];
  const float* b_fc2_1= (const float*)d_in[26];

  float* out0 = (float*)d_out;
  float* out1 = (float*)d_out + (size_t)ROWS*CDIM;

  float *ln0, *ln1, *qkv0, *qkv1, *att0, *att1, *lk0, *lk1, *lq0, *lq1;
  float *lg0, *lg1, *ml0, *ml1, *hid0, *hid1;
  cudaGetSymbolAddress((void**)&ln0,  g_ln);     ln1  = ln0  + (size_t)ROWS*CDIM;
  cudaGetSymbolAddress((void**)&qkv0, g_qkv);    qkv1 = qkv0 + (size_t)ROWS*QKVD;
  cudaGetSymbolAddress((void**)&att0, g_att);    att1 = att0 + (size_t)ROWS*CDIM;
  cudaGetSymbolAddress((void**)&lk0,  g_lk);     lk1  = lk0  + (size_t)BHN*NBKT;
  cudaGetSymbolAddress((void**)&lq0,  g_lq);     lq1  = lq0  + (size_t)BHN*NBKT;
  cudaGetSymbolAddress((void**)&lg0,  g_logits); lg1  = lg0  + (size_t)32*NQ*NQ;
  cudaGetSymbolAddress((void**)&ml0,  g_ml);     ml1  = ml0  + (size_t)BHN;
  cudaGetSymbolAddress((void**)&hid0, g_hid);    hid1 = hid0 + (size_t)ROWS*HID;

  const int LOGITS_SMEM = 18688 * 4;  // 74752 B
  const int PV_SMEM     = 18816 * 4;  // 75264 B
  static int attr_done = 0;
  if (!attr_done){
    cudaFuncSetAttribute(logits_kernel, cudaFuncAttributeMaxDynamicSharedMemorySize, LOGITS_SMEM);
    cudaFuncSetAttribute(pv_kernel,     cudaFuncAttributeMaxDynamicSharedMemorySize, PV_SMEM);
    attr_done = 1;
  }

  // 1. LN for qkv inputs
  ln_kernel<<<ROWS, 128>>>(x0, ln00_g, ln00_b, ln0);
  ln_kernel<<<ROWS, 128>>>(x1, ln01_g, ln01_b, ln1);

  // 2. qkv GEMMs
  dim3 gqkv(QKVD/128, ROWS/128);
  sgemm_kernel<<<gqkv, 256>>>(ln0, w_qkv0, b_qkv0, nullptr, qkv0, ROWS, QKVD, CDIM, 0);
  sgemm_kernel<<<gqkv, 256>>>(ln1, w_qkv1, b_qkv1, nullptr, qkv1, ROWS, QKVD, CDIM, 0);

  // 3. bias tables LK/LQ
  dim3 gbt((BHN + 2)/3, 2, 2);
  biastab_kernel<<<gbt, dim3(81,3)>>>(qkv0, qkv1, table_q, table_k);

  // 4. logits (stream 0: q0 x k1 ; stream 1: q1 x k0)
  dim3 glg(16, 16, 32);
  logits_kernel<<<glg, 256, LOGITS_SMEM>>>(qkv0, qkv1, lk0, lq0, lg0);
  logits_kernel<<<glg, 256, LOGITS_SMEM>>>(qkv1, qkv0, lk1, lq1, lg1);

  // 5. row max
  smax_kernel<<<BHN, 256>>>(lg0, ml0);
  smax_kernel<<<BHN, 256>>>(lg1, ml1);

  // 6. PV + relative-position V table (row sums derived from bucket sums)
  dim3 gpv(16, 32);
  pv_kernel<<<gpv, 256, PV_SMEM>>>(lg0, ml0, qkv1, table_v, att0);
  pv_kernel<<<gpv, 256, PV_SMEM>>>(lg1, ml1, qkv0, table_v, att1);

  // 7. proj + residual -> out
  dim3 gproj(CDIM/128, ROWS/128);
  sgemm_kernel<<<gproj, 256>>>(att0, w_proj, b_proj, x0, out0, ROWS, CDIM, CDIM, 0);
  sgemm_kernel<<<gproj, 256>>>(att1, w_proj, b_proj, x1, out1, ROWS, CDIM, CDIM, 0);

  // 8. MLP: LN -> fc1(gelu) -> fc2(+resid)
  ln_kernel<<<ROWS, 128>>>(out0, ln10_g, ln10_b, ln0);
  ln_kernel<<<ROWS, 128>>>(out1, ln11_g, ln11_b, ln1);

  dim3 gfc1(HID/128, ROWS/128);
  sgemm_kernel<<<gfc1, 256>>>(ln0, w_fc1_0, b_fc1_0, nullptr, hid0, ROWS, HID, CDIM, 1);
  sgemm_kernel<<<gfc1, 256>>>(ln1, w_fc1_1, b_fc1_1, nullptr, hid1, ROWS, HID, CDIM, 1);

  dim3 gfc2(CDIM/128, ROWS/128);
  sgemm_kernel<<<gfc2, 256>>>(hid0, w_fc2_0, b_fc2_0, out0, out0, ROWS, CDIM, HID, 0);
  sgemm_kernel<<<gfc2, 256>>>(hid1, w_fc2_1, b_fc2_1, out1, out1, ROWS, CDIM, HID, 0);
}

// round 5
// speedup vs baseline: 1.9598x; 1.9098x over previous
#include <cuda_runtime.h>
#include <cuda_bf16.h>
#include <math.h>
#include <stdint.h>

// ---------------- problem constants ----------------
#define ROWS 4096        // B*N
#define CDIM 512
#define QKVD 1536
#define HID  2048
#define NHEAD 8
#define HD   64
#define NQ   1024
#define BHN  32768       // B*H*N = 32*1024
#define NBKT 81

// ---------------- device scratch (no allocations allowed) ----------------
__device__ float g_ln    [2][ROWS*CDIM];
__device__ float g_qkv   [2][ROWS*QKVD];
__device__ float g_att   [2][ROWS*CDIM];
__device__ float g_lk    [2][(size_t)BHN*NBKT];
__device__ float g_lq    [2][(size_t)BHN*NBKT];
__device__ float g_logits[2][(size_t)32*NQ*NQ];
__device__ float g_ml    [2][BHN];
__device__ float g_hid   [2][(size_t)ROWS*HID];

// piecewise_index(d) for d=-31..31 (ALPHA=1.9, BETA=3.8, GAMMA=15.2)
__constant__ signed char c_pidx[63] = {
  -4,-4,-4,-4,-4,-4,-4,-4,-4,-4,-4,-4,-4,-4,-4,-4,-4,-4,-4,-4,-4,
  -3,-3,-3,-3,-3,-3,-3,
  -2,-2,
  -1,
   0,
   1,
   2, 2,
   3, 3, 3, 3, 3, 3, 3,
   4, 4, 4, 4, 4, 4, 4, 4, 4, 4, 4, 4, 4, 4, 4, 4, 4, 4, 4, 4, 4
};

// fast exp on FMA pipe (input <= 0 after max subtraction)
__device__ __forceinline__ float fexp(float x){
  float y = x * 1.4426950408889634f;
  float n = rintf(y);
  float f = y - n;
  float p =           1.3333558e-3f;
  p = fmaf(p, f, 9.6181291e-3f);
  p = fmaf(p, f, 5.5504108e-2f);
  p = fmaf(p, f, 2.4022650e-1f);
  p = fmaf(p, f, 6.9314718e-1f);
  p = fmaf(p, f, 1.0f);
  int ni = (int)n;
  return p * __int_as_float((ni + 127) << 23);
}

// ---------------- layernorm ------------------------------------------------
__global__ void ln_kernel(const float* __restrict__ x, const float* __restrict__ gam,
                          const float* __restrict__ bet, float* __restrict__ y)
{
  int row = blockIdx.x;
  int t = threadIdx.x;
  const float* xr = x + (size_t)row * CDIM;
  float4 v = *(const float4*)(xr + t*4);
  float s  = v.x + v.y + v.z + v.w;
  float s2 = v.x*v.x + v.y*v.y + v.z*v.z + v.w*v.w;
  #pragma unroll
  for (int o = 16; o > 0; o >>= 1){
    s  += __shfl_xor_sync(0xffffffffu, s , o);
    s2 += __shfl_xor_sync(0xffffffffu, s2, o);
  }
  __shared__ float rs[4], rq[4];
  if ((t & 31) == 0){ rs[t>>5] = s; rq[t>>5] = s2; }
  __syncthreads();
  s  = rs[0]+rs[1]+rs[2]+rs[3];
  s2 = rq[0]+rq[1]+rq[2]+rq[3];
  float mu   = s  * (1.0f/CDIM);
  float var  = s2 * (1.0f/CDIM) - mu*mu;
  float rstd = rsqrtf(var + 1e-5f);
  float4 g4 = *(const float4*)(gam + t*4);
  float4 b4 = *(const float4*)(bet + t*4);
  float4 o4;
  o4.x = (v.x-mu)*rstd*g4.x + b4.x;
  o4.y = (v.y-mu)*rstd*g4.y + b4.y;
  o4.z = (v.z-mu)*rstd*g4.z + b4.z;
  o4.w = (v.w-mu)*rstd*g4.w + b4.w;
  *(float4*)(y + (size_t)row*CDIM + t*4) = o4;
}

// ---------------- fp32 SGEMM: C = A(MxK)@B(KxN) + bias [gelu] [+resid] ----
__global__ void __launch_bounds__(256, 2) sgemm_kernel(
    const float* __restrict__ A, const float* __restrict__ Bm,
    const float* __restrict__ bias, const float* __restrict__ resid,
    float* __restrict__ C, int M, int N, int K, int gelu)
{
  __shared__ float As[8][128];
  __shared__ float Bs[8][128];
  int t  = threadIdx.x;
  int bn = blockIdx.x * 128;
  int bm = blockIdx.y * 128;
  int tx = t & 15, ty = t >> 4;

  int arow = t >> 1, acol = (t & 1) << 2;
  int brow = t >> 5, bcol = (t & 31) << 2;

  const float* Ag = A  + (size_t)(bm + arow) * K + acol;
  const float* Bg = Bm + (size_t)brow * N + bn + bcol;

  float acc[8][8];
  #pragma unroll
  for (int i = 0; i < 8; i++)
    #pragma unroll
    for (int j = 0; j < 8; j++) acc[i][j] = 0.f;

  float4 av = *(const float4*)Ag;
  float4 bv = *(const float4*)Bg;

  for (int k0 = 0; k0 < K; k0 += 8){
    As[acol+0][arow] = av.x;
    As[acol+1][arow] = av.y;
    As[acol+2][arow] = av.z;
    As[acol+3][arow] = av.w;
    *(float4*)&Bs[brow][bcol] = bv;
    __syncthreads();
    if (k0 + 8 < K){
      av = *(const float4*)(Ag + k0 + 8);
      bv = *(const float4*)(Bg + (size_t)(k0 + 8) * N);
    }
    #pragma unroll
    for (int k = 0; k < 8; k++){
      float4 a0 = *(const float4*)&As[k][ty*4];
      float4 a1 = *(const float4*)&As[k][ty*4 + 64];
      float4 b0 = *(const float4*)&Bs[k][tx*4];
      float4 b1 = *(const float4*)&Bs[k][tx*4 + 64];
      float ar[8] = {a0.x,a0.y,a0.z,a0.w,a1.x,a1.y,a1.z,a1.w};
      float br[8] = {b0.x,b0.y,b0.z,b0.w,b1.x,b1.y,b1.z,b1.w};
      #pragma unroll
      for (int i = 0; i < 8; i++)
        #pragma unroll
        for (int j = 0; j < 8; j++) acc[i][j] += ar[i]*br[j];
    }
    __syncthreads();
  }

  float4 bias0 = *(const float4*)(bias + bn + tx*4);
  float4 bias1 = *(const float4*)(bias + bn + tx*4 + 64);
  float bb[8] = {bias0.x,bias0.y,bias0.z,bias0.w,bias1.x,bias1.y,bias1.z,bias1.w};

  #pragma unroll
  for (int i = 0; i < 8; i++){
    int row = bm + (ty<<2) + (i & 3) + ((i >> 2) << 6);
    #pragma unroll
    for (int jh = 0; jh < 2; jh++){
      int col = bn + (tx<<2) + (jh<<6);
      float r0 = acc[i][jh*4+0] + bb[jh*4+0];
      float r1 = acc[i][jh*4+1] + bb[jh*4+1];
      float r2 = acc[i][jh*4+2] + bb[jh*4+2];
      float r3 = acc[i][jh*4+3] + bb[jh*4+3];
      if (gelu){
        r0 = 0.5f*r0*(1.0f + erff(r0*0.70710678f));
        r1 = 0.5f*r1*(1.0f + erff(r1*0.70710678f));
        r2 = 0.5f*r2*(1.0f + erff(r2*0.70710678f));
        r3 = 0.5f*r3*(1.0f + erff(r3*0.70710678f));
      }
      if (resid){
        const float4 rr = *(const float4*)(resid + (size_t)row*N + col);
        r0 += rr.x; r1 += rr.y; r2 += rr.z; r3 += rr.w;
      }
      *(float4*)(C + (size_t)row*N + col) = make_float4(r0,r1,r2,r3);
    }
  }
}

// ---------------- bias tables as tiled GEMM: 64 rows x 81 cols x K=64 ------
// grid (BHN/64, which, stream), block 256
// smem: qs[64][65] + tabT[64][84]
__global__ void __launch_bounds__(256) biastab_kernel(
    const float* __restrict__ qkv0, const float* __restrict__ qkv1,
    const float* __restrict__ tq, const float* __restrict__ tk,
    float* __restrict__ lk0, float* __restrict__ lk1,
    float* __restrict__ lq0, float* __restrict__ lq1)
{
  __shared__ float qs[64*65];
  __shared__ float tabT[64*84];

  int t = threadIdx.x;
  int s = blockIdx.z, which = blockIdx.y;
  int base = blockIdx.x << 6;              // first rid of this tile
  const float* src;
  float scl;
  if (which == 0){ src = (s == 0 ? qkv0 : qkv1);       scl = 1.0f;   }  // Q of stream s
  else           { src = (s == 0 ? qkv1 : qkv0) + 512; scl = 0.125f; }  // K of other stream
  const float* tab = (which == 0) ? tk : tq;

  // stage table transposed: tabT[d][c] = tab[c*64+d]
  for (int idx = t; idx < NBKT*64; idx += 256){
    int c = idx >> 6, d = idx & 63;
    tabT[d*84 + c] = tab[idx];
  }
  // stage 64 q rows (scaled)
  #pragma unroll
  for (int it = 0; it < 4; it++){
    int f = t + (it<<8);
    int r = f >> 4, c4 = (f & 15) << 2;
    int rid = base + r;
    int bh = rid >> 10, n = rid & 1023;
    int b = bh >> 3, h = bh & 7;
    float4 v = *(const float4*)(src + (size_t)((b<<10)+n)*QKVD + (h<<6) + c4);
    qs[r*65+c4+0] = scl*v.x; qs[r*65+c4+1] = scl*v.y;
    qs[r*65+c4+2] = scl*v.z; qs[r*65+c4+3] = scl*v.w;
  }
  __syncthreads();

  int tx = t & 31, ty = t >> 5;   // ty: 8 row-groups of 8; tx: cols {tx, tx+32, tx+64}
  float acc[8][3];
  #pragma unroll
  for (int i=0;i<8;i++){ acc[i][0]=0.f; acc[i][1]=0.f; acc[i][2]=0.f; }

  #pragma unroll 8
  for (int k = 0; k < 64; k++){
    float b0 = tabT[k*84 + tx];
    float b1 = tabT[k*84 + tx + 32];
    float b2 = (tx < 17) ? tabT[k*84 + tx + 64] : 0.f;
    #pragma unroll
    for (int i = 0; i < 8; i++){
      float a = qs[((ty<<3)+i)*65 + k];
      acc[i][0] = fmaf(a, b0, acc[i][0]);
      acc[i][1] = fmaf(a, b1, acc[i][1]);
      acc[i][2] = fmaf(a, b2, acc[i][2]);
    }
  }

  float* dstbase = (which == 0) ? (s == 0 ? lk0 : lk1) : (s == 0 ? lq0 : lq1);
  #pragma unroll
  for (int i = 0; i < 8; i++){
    int rid = base + (ty<<3) + i;
    float* dst = dstbase + (size_t)rid*NBKT;
    dst[tx]      = acc[i][0];
    dst[tx + 32] = acc[i][1];
    if (tx < 17) dst[tx + 64] = acc[i][2];
  }
}

// ---------------- attention logits: 64x64 tile, smem-staged bias tables ----
__global__ void __launch_bounds__(256) logits_kernel(
    const float* __restrict__ qkv_q, const float* __restrict__ qkv_k,
    const float* __restrict__ LK, const float* __restrict__ LQ,
    float* __restrict__ S)
{
  extern __shared__ float sm[];
  float* qs  = sm;           // [64][65]
  float* ks  = sm + 4160;    // [64][65]
  float* lks = sm + 8320;    // [64][81]
  float* lqs = sm + 13504;   // [64][81]

  int t = threadIdx.x;
  int bh = blockIdx.z; int b = bh>>3, h = bh&7;
  int i0 = blockIdx.y<<6, j0 = blockIdx.x<<6;
  size_t rbase = ((size_t)bh)<<10;
  const float* qb = qkv_q + (size_t)(b<<10)*QKVD + (h<<6);
  const float* kb = qkv_k + (size_t)(b<<10)*QKVD + (h<<6) + 512;
  #pragma unroll
  for (int it = 0; it < 4; it++){
    int f = t + (it<<8);
    int r = f >> 4, c4 = (f & 15) << 2;
    float4 qv = *(const float4*)(qb + (size_t)(i0+r)*QKVD + c4);
    float4 kv = *(const float4*)(kb + (size_t)(j0+r)*QKVD + c4);
    qs[r*65+c4+0]=qv.x; qs[r*65+c4+1]=qv.y; qs[r*65+c4+2]=qv.z; qs[r*65+c4+3]=qv.w;
    ks[r*65+c4+0]=kv.x; ks[r*65+c4+1]=kv.y; ks[r*65+c4+2]=kv.z; ks[r*65+c4+3]=kv.w;
  }
  for (int f = t; f < 64*NBKT; f += 256){
    int r = f / NBKT, c = f - r*NBKT;
    lks[f] = LK[(rbase + i0 + r)*NBKT + c];
    lqs[f] = LQ[(rbase + j0 + r)*NBKT + c];
  }
  __syncthreads();

  int tx = t & 15, ty = t >> 4;
  float acc[4][4];
  #pragma unroll
  for (int i=0;i<4;i++)
    #pragma unroll
    for(int j=0;j<4;j++) acc[i][j]=0.f;
  #pragma unroll
  for (int k = 0; k < 64; k++){
    float a[4], bb[4];
    #pragma unroll
    for (int ii=0; ii<4; ii++) a[ii] = qs[((ty<<2)+ii)*65 + k];
    #pragma unroll
    for (int jj=0; jj<4; jj++) bb[jj] = ks[((tx<<2)+jj)*65 + k];
    #pragma unroll
    for (int ii=0;ii<4;ii++)
      #pragma unroll
      for(int jj=0;jj<4;jj++) acc[ii][jj] += a[ii]*bb[jj];
  }
  #pragma unroll
  for (int ii=0; ii<4; ii++){
    int il = (ty<<2)+ii;
    int i = i0 + il;
    int yi = i >> 5, xi = i & 31;
    #pragma unroll
    for (int jj=0; jj<4; jj++){
      int jl = (tx<<2)+jj;
      int j = j0 + jl;
      int dy = yi - (j>>5), dx = xi - (j&31);
      int bkt = ((int)c_pidx[dy+31]+4)*9 + ((int)c_pidx[dx+31]+4);
      float v = acc[ii][jj]*0.125f + lks[il*NBKT + bkt] + lqs[jl*NBKT + 80 - bkt];
      S[(rbase + i)*NQ + j] = v;
    }
  }
}

// ---------------- row max only ---------------------------------------------
__global__ void smax_kernel(const float* __restrict__ S, float* __restrict__ ml)
{
  int rid = blockIdx.x;
  int t = threadIdx.x; // 256
  const float4 a = ((const float4*)(S + (size_t)rid*NQ))[t];
  float m = fmaxf(fmaxf(a.x,a.y), fmaxf(a.z,a.w));
  #pragma unroll
  for (int o=16;o>0;o>>=1) m = fmaxf(m, __shfl_xor_sync(0xffffffffu,m,o));
  __shared__ float rm[8];
  if ((t&31)==0) rm[t>>5] = m;
  __syncthreads();
  if (t==0){
    m = rm[0];
    #pragma unroll
    for (int w=1;w<8;w++) m = fmaxf(m, rm[w]);
    ml[rid] = m;
  }
}

// ---------------- PV: 64x64 tile GEMM + run-length bucket scatter ----------
__global__ void __launch_bounds__(256) pv_kernel(
    const float* __restrict__ S, const float* __restrict__ ml,
    const float* __restrict__ qkv_v, const float* __restrict__ tv,
    float* __restrict__ out)
{
  extern __shared__ float sm[];
  float* ps  = sm;            // [64][65]
  float* vs  = sm + 4160;     // [64][65]
  float* sb  = sm + 8320;     // [64][81]
  float* tvs = sm + 13504;    // [81][64]
  float* mrow= sm + 18688;    // [64]
  float* rsv = sm + 18752;    // [64]

  int t = threadIdx.x;
  int bh = blockIdx.y; int b = bh>>3, h = bh&7;
  int i0 = blockIdx.x << 6;
  size_t rb2 = (((size_t)bh)<<10) + i0;
  if (t < 64) mrow[t] = ml[rb2 + t];
  for (int f = t; f < 64*NBKT; f += 256) sb[f] = 0.f;
  for (int f = t; f < NBKT*64; f += 256) tvs[f] = tv[f];
  __syncthreads();

  int tx = t & 15, ty = t >> 4;
  float acc[4][4];
  #pragma unroll
  for (int i=0;i<4;i++)
    #pragma unroll
    for(int d=0;d<4;d++) acc[i][d]=0.f;
  const float* vb = qkv_v + ((size_t)(b<<10))*QKVD + (h<<6) + 1024;

  int sr = t >> 2;
  int q0 = (t & 3) << 4;
  int iglob = i0 + sr;
  int syi = iglob >> 5, sxi = iglob & 31;

  for (int jt = 0; jt < 16; jt++){
    int j0 = jt << 6;
    #pragma unroll
    for (int it = 0; it < 4; it++){
      int f = t + (it<<8);
      int r = f >> 4, c4 = (f&15)<<2;
      float4 sv = *(const float4*)(S + (rb2 + r)*NQ + j0 + c4);
      float m = mrow[r];
      ps[r*65+c4+0] = fexp(sv.x - m);
      ps[r*65+c4+1] = fexp(sv.y - m);
      ps[r*65+c4+2] = fexp(sv.z - m);
      ps[r*65+c4+3] = fexp(sv.w - m);
      float4 vv = *(const float4*)(vb + (size_t)(j0+r)*QKVD + c4);
      vs[r*65+c4+0]=vv.x; vs[r*65+c4+1]=vv.y; vs[r*65+c4+2]=vv.z; vs[r*65+c4+3]=vv.w;
    }
    __syncthreads();

    {
      float runv = 0.f; int runb = -1;
      #pragma unroll
      for (int q = 0; q < 16; q++){
        int jj = q0 + q;
        int j = j0 + jj;
        int dy = syi - (j>>5), dx = sxi - (j&31);
        int bkt = ((int)c_pidx[dy+31]+4)*9 + ((int)c_pidx[dx+31]+4);
        float pvv = ps[sr*65 + jj];
        if (bkt == runb) runv += pvv;
        else {
          if (runb >= 0) atomicAdd(&sb[sr*NBKT + runb], runv);
          runb = bkt; runv = pvv;
        }
      }
      atomicAdd(&sb[sr*NBKT + runb], runv);
    }

    #pragma unroll
    for (int k = 0; k < 64; k++){
      float bv[4], a[4];
      #pragma unroll
      for (int dd=0; dd<4; dd++) bv[dd] = vs[k*65 + (tx<<2)+dd];
      #pragma unroll
      for (int ii=0; ii<4; ii++) a[ii] = ps[((ty<<2)+ii)*65 + k];
      #pragma unroll
      for (int ii=0;ii<4;ii++)
        #pragma unroll
        for (int dd=0;dd<4;dd++) acc[ii][dd] += a[ii]*bv[dd];
    }
    __syncthreads();
  }

  if (t < 64){
    float s = 0.f;
    #pragma unroll
    for (int c = 0; c < NBKT; c++) s += sb[t*NBKT + c];
    rsv[t] = 1.0f / s;
  }
  __syncthreads();

  #pragma unroll
  for (int ii=0; ii<4; ii++){
    int r = (ty<<2)+ii;
    float inv = rsv[r];
    float o0=acc[ii][0]*inv, o1=acc[ii][1]*inv, o2=acc[ii][2]*inv, o3=acc[ii][3]*inv;
    for (int c = 0; c < NBKT; c++){
      float svc = sb[r*NBKT + c] * inv;
      float4 tvv = *(const float4*)&tvs[(c<<6) + (tx<<2)];
      o0 = fmaf(svc, tvv.x, o0); o1 = fmaf(svc, tvv.y, o1);
      o2 = fmaf(svc, tvv.z, o2); o3 = fmaf(svc, tvv.w, o3);
    }
    float* op = out + ((size_t)(b<<10) + i0 + r)*CDIM + (h<<6) + (tx<<2);
    *(float4*)op = make_float4(o0,o1,o2,o3);
  }
}

// ---------------- launch ----------------------------------------------------
extern "C" void kernel_launch(void* const* d_in, const int* in_sizes, int n_in,
                              void* d_out, int out_size)
{
  const float* x0     = (const float*)d_in[0];
  const float* x1     = (const float*)d_in[1];
  const float* ln00_g = (const float*)d_in[2];
  const float* ln00_b = (const float*)d_in[3];
  const float* ln01_g = (const float*)d_in[4];
  const float* ln01_b = (const float*)d_in[5];
  const float* ln10_g = (const float*)d_in[6];
  const float* ln10_b = (const float*)d_in[7];
  const float* ln11_g = (const float*)d_in[8];
  const float* ln11_b = (const float*)d_in[9];
  const float* w_qkv0 = (const float*)d_in[10];
  const float* b_qkv0 = (const float*)d_in[11];
  const float* w_qkv1 = (const float*)d_in[12];
  const float* b_qkv1 = (const float*)d_in[13];
  const float* w_proj = (const float*)d_in[14];
  const float* b_proj = (const float*)d_in[15];
  const float* table_q= (const float*)d_in[16];
  const float* table_k= (const float*)d_in[17];
  const float* table_v= (const float*)d_in[18];
  const float* w_fc1_0= (const float*)d_in[19];
  const float* b_fc1_0= (const float*)d_in[20];
  const float* w_fc2_0= (const float*)d_in[21];
  const float* b_fc2_0= (const float*)d_in[22];
  const float* w_fc1_1= (const float*)d_in[23];
  const float* b_fc1_1= (const float*)d_in[24];
  const float* w_fc2_1= (const float*)d_in[25];
  const float* b_fc2_1= (const float*)d_in[26];

  float* out0 = (float*)d_out;
  float* out1 = (float*)d_out + (size_t)ROWS*CDIM;

  float *ln0, *ln1, *qkv0, *qkv1, *att0, *att1, *lk0, *lk1, *lq0, *lq1;
  float *lg0, *lg1, *ml0, *ml1, *hid0, *hid1;
  cudaGetSymbolAddress((void**)&ln0,  g_ln);     ln1  = ln0  + (size_t)ROWS*CDIM;
  cudaGetSymbolAddress((void**)&qkv0, g_qkv);    qkv1 = qkv0 + (size_t)ROWS*QKVD;
  cudaGetSymbolAddress((void**)&att0, g_att);    att1 = att0 + (size_t)ROWS*CDIM;
  cudaGetSymbolAddress((void**)&lk0,  g_lk);     lk1  = lk0  + (size_t)BHN*NBKT;
  cudaGetSymbolAddress((void**)&lq0,  g_lq);     lq1  = lq0  + (size_t)BHN*NBKT;
  cudaGetSymbolAddress((void**)&lg0,  g_logits); lg1  = lg0  + (size_t)32*NQ*NQ;
  cudaGetSymbolAddress((void**)&ml0,  g_ml);     ml1  = ml0  + (size_t)BHN;
  cudaGetSymbolAddress((void**)&hid0, g_hid);    hid1 = hid0 + (size_t)ROWS*HID;

  const int LOGITS_SMEM = 18688 * 4;  // 74752 B
  const int PV_SMEM     = 18816 * 4;  // 75264 B
  static int attr_done = 0;
  if (!attr_done){
    cudaFuncSetAttribute(logits_kernel, cudaFuncAttributeMaxDynamicSharedMemorySize, LOGITS_SMEM);
    cudaFuncSetAttribute(pv_kernel,     cudaFuncAttributeMaxDynamicSharedMemorySize, PV_SMEM);
    attr_done = 1;
  }

  // 1. LN for qkv inputs
  ln_kernel<<<ROWS, 128>>>(x0, ln00_g, ln00_b, ln0);
  ln_kernel<<<ROWS, 128>>>(x1, ln01_g, ln01_b, ln1);

  // 2. qkv GEMMs
  dim3 gqkv(QKVD/128, ROWS/128);
  sgemm_kernel<<<gqkv, 256>>>(ln0, w_qkv0, b_qkv0, nullptr, qkv0, ROWS, QKVD, CDIM, 0);
  sgemm_kernel<<<gqkv, 256>>>(ln1, w_qkv1, b_qkv1, nullptr, qkv1, ROWS, QKVD, CDIM, 0);

  // 3. bias tables LK/LQ (tiled GEMM)
  dim3 gbt(BHN/64, 2, 2);
  biastab_kernel<<<gbt, 256>>>(qkv0, qkv1, table_q, table_k, lk0, lk1, lq0, lq1);

  // 4. logits
  dim3 glg(16, 16, 32);
  logits_kernel<<<glg, 256, LOGITS_SMEM>>>(qkv0, qkv1, lk0, lq0, lg0);
  logits_kernel<<<glg, 256, LOGITS_SMEM>>>(qkv1, qkv0, lk1, lq1, lg1);

  // 5. row max
  smax_kernel<<<BHN, 256>>>(lg0, ml0);
  smax_kernel<<<BHN, 256>>>(lg1, ml1);

  // 6. PV + relative-position V table
  dim3 gpv(16, 32);
  pv_kernel<<<gpv, 256, PV_SMEM>>>(lg0, ml0, qkv1, table_v, att0);
  pv_kernel<<<gpv, 256, PV_SMEM>>>(lg1, ml1, qkv0, table_v, att1);

  // 7. proj + residual -> out
  dim3 gproj(CDIM/128, ROWS/128);
  sgemm_kernel<<<gproj, 256>>>(att0, w_proj, b_proj, x0, out0, ROWS, CDIM, CDIM, 0);
  sgemm_kernel<<<gproj, 256>>>(att1, w_proj, b_proj, x1, out1, ROWS, CDIM, CDIM, 0);

  // 8. MLP
  ln_kernel<<<ROWS, 128>>>(out0, ln10_g, ln10_b, ln0);
  ln_kernel<<<ROWS, 128>>>(out1, ln11_g, ln11_b, ln1);

  dim3 gfc1(HID/128, ROWS/128);
  sgemm_kernel<<<gfc1, 256>>>(ln0, w_fc1_0, b_fc1_0, nullptr, hid0, ROWS, HID, CDIM, 1);
  sgemm_kernel<<<gfc1, 256>>>(ln1, w_fc1_1, b_fc1_1, nullptr, hid1, ROWS, HID, CDIM, 1);

  dim3 gfc2(CDIM/128, ROWS/128);
  sgemm_kernel<<<gfc2, 256>>>(hid0, w_fc2_0, b_fc2_0, out0, out0, ROWS, CDIM, HID, 0);
  sgemm_kernel<<<gfc2, 256>>>(hid1, w_fc2_1, b_fc2_1, out1, out1, ROWS, CDIM, HID, 0);
}

// round 6
// speedup vs baseline: 2.4137x; 1.2316x over previous
#include <cuda_runtime.h>
#include <cuda_bf16.h>
#include <math.h>
#include <stdint.h>

// ---------------- problem constants ----------------
#define ROWS 4096        // B*N
#define CDIM 512
#define QKVD 1536
#define HID  2048
#define NHEAD 8
#define HD   64
#define NQ   1024
#define BHN  32768       // B*H*N = 32*1024
#define NBKT 81

// ---------------- device scratch (no allocations allowed) ----------------
__device__ float g_ln    [2][ROWS*CDIM];
__device__ float g_qkv   [2][ROWS*QKVD];
__device__ float g_att   [2][ROWS*CDIM];
__device__ float g_lk    [2][(size_t)BHN*NBKT];
__device__ float g_lq    [2][(size_t)BHN*NBKT];
__device__ float g_logits[2][(size_t)32*NQ*NQ];
__device__ float g_ml    [2][BHN];
__device__ float g_hid   [2][(size_t)ROWS*HID];

// piecewise_index(d) for d=-31..31 (ALPHA=1.9, BETA=3.8, GAMMA=15.2)
__constant__ signed char c_pidx[63] = {
  -4,-4,-4,-4,-4,-4,-4,-4,-4,-4,-4,-4,-4,-4,-4,-4,-4,-4,-4,-4,-4,
  -3,-3,-3,-3,-3,-3,-3,
  -2,-2,
  -1,
   0,
   1,
   2, 2,
   3, 3, 3, 3, 3, 3, 3,
   4, 4, 4, 4, 4, 4, 4, 4, 4, 4, 4, 4, 4, 4, 4, 4, 4, 4, 4, 4, 4
};

// fast exp on FMA pipe
__device__ __forceinline__ float fexp(float x){
  float y = x * 1.4426950408889634f;
  float n = rintf(y);
  float f = y - n;
  float p =           1.3333558e-3f;
  p = fmaf(p, f, 9.6181291e-3f);
  p = fmaf(p, f, 5.5504108e-2f);
  p = fmaf(p, f, 2.4022650e-1f);
  p = fmaf(p, f, 6.9314718e-1f);
  p = fmaf(p, f, 1.0f);
  int ni = (int)n;
  return p * __int_as_float((ni + 127) << 23);
}

__device__ __forceinline__ uint32_t f2tf32(float v){
  uint32_t r;
  asm("cvt.rna.tf32.f32 %0, %1;" : "=r"(r) : "f"(v));
  return r;
}

// ---------------- layernorm ------------------------------------------------
__global__ void ln_kernel(const float* __restrict__ x, const float* __restrict__ gam,
                          const float* __restrict__ bet, float* __restrict__ y)
{
  int row = blockIdx.x;
  int t = threadIdx.x;
  const float* xr = x + (size_t)row * CDIM;
  float4 v = *(const float4*)(xr + t*4);
  float s  = v.x + v.y + v.z + v.w;
  float s2 = v.x*v.x + v.y*v.y + v.z*v.z + v.w*v.w;
  #pragma unroll
  for (int o = 16; o > 0; o >>= 1){
    s  += __shfl_xor_sync(0xffffffffu, s , o);
    s2 += __shfl_xor_sync(0xffffffffu, s2, o);
  }
  __shared__ float rs[4], rq[4];
  if ((t & 31) == 0){ rs[t>>5] = s; rq[t>>5] = s2; }
  __syncthreads();
  s  = rs[0]+rs[1]+rs[2]+rs[3];
  s2 = rq[0]+rq[1]+rq[2]+rq[3];
  float mu   = s  * (1.0f/CDIM);
  float var  = s2 * (1.0f/CDIM) - mu*mu;
  float rstd = rsqrtf(var + 1e-5f);
  float4 g4 = *(const float4*)(gam + t*4);
  float4 b4 = *(const float4*)(bet + t*4);
  float4 o4;
  o4.x = (v.x-mu)*rstd*g4.x + b4.x;
  o4.y = (v.y-mu)*rstd*g4.y + b4.y;
  o4.z = (v.z-mu)*rstd*g4.z + b4.z;
  o4.w = (v.w-mu)*rstd*g4.w + b4.w;
  *(float4*)(y + (size_t)row*CDIM + t*4) = o4;
}

// ---------------- tf32 tensor-core GEMM: C = A@B + bias [gelu] [+resid] ----
// 128x128x16 tile, 8 warps (2x4), warp tile 64x32 via m16n8k8 mma.
__global__ void __launch_bounds__(256, 2) sgemm_tf32_kernel(
    const float* __restrict__ A, const float* __restrict__ Bm,
    const float* __restrict__ bias, const float* __restrict__ resid,
    float* __restrict__ C, int M, int N, int K, int gelu)
{
  __shared__ float As[16][132];   // A staged transposed: As[k][m]
  __shared__ float Bs[16][132];   // Bs[k][n]
  int t = threadIdx.x;
  int bn = blockIdx.x * 128;
  int bm = blockIdx.y * 128;
  int warp = t >> 5, lane = t & 31;
  int wm = (warp >> 2) << 6;      // 0 or 64
  int wn = (warp & 3) << 5;       // 0,32,64,96
  int g  = lane >> 2;             // groupID 0..7
  int tg = lane & 3;              // 0..3

  float acc[4][4][4];
  #pragma unroll
  for (int mt=0;mt<4;mt++)
    #pragma unroll
    for (int nt=0;nt<4;nt++)
      #pragma unroll
      for (int c=0;c<4;c++) acc[mt][nt][c] = 0.f;

  const float* Ag = A + (size_t)bm * K;
  const float* Bg = Bm + bn;

  for (int k0 = 0; k0 < K; k0 += 16){
    #pragma unroll
    for (int i = 0; i < 2; i++){
      int f = (t<<1) + i;
      int r = f >> 2, kc = (f & 3) << 2;                       // A: row r, k cols kc..kc+3
      float4 v = *(const float4*)(Ag + (size_t)r*K + k0 + kc);
      As[kc+0][r] = __uint_as_float(f2tf32(v.x));
      As[kc+1][r] = __uint_as_float(f2tf32(v.y));
      As[kc+2][r] = __uint_as_float(f2tf32(v.z));
      As[kc+3][r] = __uint_as_float(f2tf32(v.w));
      int kr = f >> 5, nc = (f & 31) << 2;                     // B: k row kr, n cols
      float4 w = *(const float4*)(Bg + (size_t)(k0+kr)*N + nc);
      float4 wt;
      wt.x = __uint_as_float(f2tf32(w.x));
      wt.y = __uint_as_float(f2tf32(w.y));
      wt.z = __uint_as_float(f2tf32(w.z));
      wt.w = __uint_as_float(f2tf32(w.w));
      *(float4*)&Bs[kr][nc] = wt;
    }
    __syncthreads();

    #pragma unroll
    for (int ks = 0; ks < 16; ks += 8){
      uint32_t af[4][4], bf[4][2];
      #pragma unroll
      for (int mt = 0; mt < 4; mt++){
        int m = wm + (mt<<4) + g;
        af[mt][0] = __float_as_uint(As[ks+tg  ][m]);
        af[mt][1] = __float_as_uint(As[ks+tg  ][m+8]);
        af[mt][2] = __float_as_uint(As[ks+tg+4][m]);
        af[mt][3] = __float_as_uint(As[ks+tg+4][m+8]);
      }
      #pragma unroll
      for (int nt = 0; nt < 4; nt++){
        int n = wn + (nt<<3) + g;
        bf[nt][0] = __float_as_uint(Bs[ks+tg  ][n]);
        bf[nt][1] = __float_as_uint(Bs[ks+tg+4][n]);
      }
      #pragma unroll
      for (int mt = 0; mt < 4; mt++)
        #pragma unroll
        for (int nt = 0; nt < 4; nt++){
          asm volatile(
            "mma.sync.aligned.m16n8k8.row.col.f32.tf32.tf32.f32 "
            "{%0,%1,%2,%3}, {%4,%5,%6,%7}, {%8,%9}, {%0,%1,%2,%3};"
            : "+f"(acc[mt][nt][0]), "+f"(acc[mt][nt][1]),
              "+f"(acc[mt][nt][2]), "+f"(acc[mt][nt][3])
            : "r"(af[mt][0]), "r"(af[mt][1]), "r"(af[mt][2]), "r"(af[mt][3]),
              "r"(bf[nt][0]), "r"(bf[nt][1]));
        }
    }
    __syncthreads();
  }

  // epilogue: c0,c1 -> (row, col), (row, col+1); c2,c3 -> row+8
  #pragma unroll
  for (int mt = 0; mt < 4; mt++){
    int row0 = bm + wm + (mt<<4) + g;
    #pragma unroll
    for (int nt = 0; nt < 4; nt++){
      int col = bn + wn + (nt<<3) + (tg<<1);
      float b0 = bias[col], b1 = bias[col+1];
      #pragma unroll
      for (int h = 0; h < 2; h++){
        int row = row0 + (h<<3);
        float r0 = acc[mt][nt][h*2+0] + b0;
        float r1 = acc[mt][nt][h*2+1] + b1;
        if (gelu){
          r0 = 0.5f*r0*(1.0f + erff(r0*0.70710678f));
          r1 = 0.5f*r1*(1.0f + erff(r1*0.70710678f));
        }
        if (resid){
          const float2 rr = *(const float2*)(resid + (size_t)row*N + col);
          r0 += rr.x; r1 += rr.y;
        }
        *(float2*)(C + (size_t)row*N + col) = make_float2(r0, r1);
      }
    }
  }
}

// ---------------- bias tables as tiled GEMM: 64 rows x 81 cols x K=64 ------
__global__ void __launch_bounds__(256) biastab_kernel(
    const float* __restrict__ qkv0, const float* __restrict__ qkv1,
    const float* __restrict__ tq, const float* __restrict__ tk,
    float* __restrict__ lk0, float* __restrict__ lk1,
    float* __restrict__ lq0, float* __restrict__ lq1)
{
  __shared__ float qs[64*65];
  __shared__ float tabT[64*84];

  int t = threadIdx.x;
  int s = blockIdx.z, which = blockIdx.y;
  int base = blockIdx.x << 6;
  const float* src;
  float scl;
  if (which == 0){ src = (s == 0 ? qkv0 : qkv1);       scl = 1.0f;   }
  else           { src = (s == 0 ? qkv1 : qkv0) + 512; scl = 0.125f; }
  const float* tab = (which == 0) ? tk : tq;

  for (int idx = t; idx < NBKT*64; idx += 256){
    int c = idx >> 6, d = idx & 63;
    tabT[d*84 + c] = tab[idx];
  }
  #pragma unroll
  for (int it = 0; it < 4; it++){
    int f = t + (it<<8);
    int r = f >> 4, c4 = (f & 15) << 2;
    int rid = base + r;
    int bh = rid >> 10, n = rid & 1023;
    int b = bh >> 3, h = bh & 7;
    float4 v = *(const float4*)(src + (size_t)((b<<10)+n)*QKVD + (h<<6) + c4);
    qs[r*65+c4+0] = scl*v.x; qs[r*65+c4+1] = scl*v.y;
    qs[r*65+c4+2] = scl*v.z; qs[r*65+c4+3] = scl*v.w;
  }
  __syncthreads();

  int tx = t & 31, ty = t >> 5;
  float acc[8][3];
  #pragma unroll
  for (int i=0;i<8;i++){ acc[i][0]=0.f; acc[i][1]=0.f; acc[i][2]=0.f; }

  #pragma unroll 8
  for (int k = 0; k < 64; k++){
    float b0 = tabT[k*84 + tx];
    float b1 = tabT[k*84 + tx + 32];
    float b2 = (tx < 17) ? tabT[k*84 + tx + 64] : 0.f;
    #pragma unroll
    for (int i = 0; i < 8; i++){
      float a = qs[((ty<<3)+i)*65 + k];
      acc[i][0] = fmaf(a, b0, acc[i][0]);
      acc[i][1] = fmaf(a, b1, acc[i][1]);
      acc[i][2] = fmaf(a, b2, acc[i][2]);
    }
  }

  float* dstbase = (which == 0) ? (s == 0 ? lk0 : lk1) : (s == 0 ? lq0 : lq1);
  #pragma unroll
  for (int i = 0; i < 8; i++){
    int rid = base + (ty<<3) + i;
    float* dst = dstbase + (size_t)rid*NBKT;
    dst[tx]      = acc[i][0];
    dst[tx + 32] = acc[i][1];
    if (tx < 17) dst[tx + 64] = acc[i][2];
  }
}

// ---------------- attention logits: 64x64 tile, smem-staged bias tables ----
__global__ void __launch_bounds__(256) logits_kernel(
    const float* __restrict__ qkv_q, const float* __restrict__ qkv_k,
    const float* __restrict__ LK, const float* __restrict__ LQ,
    float* __restrict__ S)
{
  extern __shared__ float sm[];
  float* qs  = sm;           // [64][65]
  float* ks  = sm + 4160;    // [64][65]
  float* lks = sm + 8320;    // [64][81]
  float* lqs = sm + 13504;   // [64][81]

  int t = threadIdx.x;
  int bh = blockIdx.z; int b = bh>>3, h = bh&7;
  int i0 = blockIdx.y<<6, j0 = blockIdx.x<<6;
  size_t rbase = ((size_t)bh)<<10;
  const float* qb = qkv_q + (size_t)(b<<10)*QKVD + (h<<6);
  const float* kb = qkv_k + (size_t)(b<<10)*QKVD + (h<<6) + 512;
  #pragma unroll
  for (int it = 0; it < 4; it++){
    int f = t + (it<<8);
    int r = f >> 4, c4 = (f & 15) << 2;
    float4 qv = *(const float4*)(qb + (size_t)(i0+r)*QKVD + c4);
    float4 kv = *(const float4*)(kb + (size_t)(j0+r)*QKVD + c4);
    qs[r*65+c4+0]=qv.x; qs[r*65+c4+1]=qv.y; qs[r*65+c4+2]=qv.z; qs[r*65+c4+3]=qv.w;
    ks[r*65+c4+0]=kv.x; ks[r*65+c4+1]=kv.y; ks[r*65+c4+2]=kv.z; ks[r*65+c4+3]=kv.w;
  }
  for (int f = t; f < 64*NBKT; f += 256){
    int r = f / NBKT, c = f - r*NBKT;
    lks[f] = LK[(rbase + i0 + r)*NBKT + c];
    lqs[f] = LQ[(rbase + j0 + r)*NBKT + c];
  }
  __syncthreads();

  int tx = t & 15, ty = t >> 4;
  float acc[4][4];
  #pragma unroll
  for (int i=0;i<4;i++)
    #pragma unroll
    for(int j=0;j<4;j++) acc[i][j]=0.f;
  #pragma unroll
  for (int k = 0; k < 64; k++){
    float a[4], bb[4];
    #pragma unroll
    for (int ii=0; ii<4; ii++) a[ii] = qs[((ty<<2)+ii)*65 + k];
    #pragma unroll
    for (int jj=0; jj<4; jj++) bb[jj] = ks[((tx<<2)+jj)*65 + k];
    #pragma unroll
    for (int ii=0;ii<4;ii++)
      #pragma unroll
      for(int jj=0;jj<4;jj++) acc[ii][jj] += a[ii]*bb[jj];
  }
  #pragma unroll
  for (int ii=0; ii<4; ii++){
    int il = (ty<<2)+ii;
    int i = i0 + il;
    int yi = i >> 5, xi = i & 31;
    #pragma unroll
    for (int jj=0; jj<4; jj++){
      int jl = (tx<<2)+jj;
      int j = j0 + jl;
      int dy = yi - (j>>5), dx = xi - (j&31);
      int bkt = ((int)c_pidx[dy+31]+4)*9 + ((int)c_pidx[dx+31]+4);
      float v = acc[ii][jj]*0.125f + lks[il*NBKT + bkt] + lqs[jl*NBKT + 80 - bkt];
      S[(rbase + i)*NQ + j] = v;
    }
  }
}

// ---------------- row max only ---------------------------------------------
__global__ void smax_kernel(const float* __restrict__ S, float* __restrict__ ml)
{
  int rid = blockIdx.x;
  int t = threadIdx.x;
  const float4 a = ((const float4*)(S + (size_t)rid*NQ))[t];
  float m = fmaxf(fmaxf(a.x,a.y), fmaxf(a.z,a.w));
  #pragma unroll
  for (int o=16;o>0;o>>=1) m = fmaxf(m, __shfl_xor_sync(0xffffffffu,m,o));
  __shared__ float rm[8];
  if ((t&31)==0) rm[t>>5] = m;
  __syncthreads();
  if (t==0){
    m = rm[0];
    #pragma unroll
    for (int w=1;w<8;w++) m = fmaxf(m, rm[w]);
    ml[rid] = m;
  }
}

// ---------------- PV: 64x64 tile GEMM + run-length bucket scatter ----------
__global__ void __launch_bounds__(256) pv_kernel(
    const float* __restrict__ S, const float* __restrict__ ml,
    const float* __restrict__ qkv_v, const float* __restrict__ tv,
    float* __restrict__ out)
{
  extern __shared__ float sm[];
  float* ps  = sm;            // [64][65]
  float* vs  = sm + 4160;     // [64][65]
  float* sb  = sm + 8320;     // [64][81]
  float* tvs = sm + 13504;    // [81][64]
  float* mrow= sm + 18688;    // [64]
  float* rsv = sm + 18752;    // [64]

  int t = threadIdx.x;
  int bh = blockIdx.y; int b = bh>>3, h = bh&7;
  int i0 = blockIdx.x << 6;
  size_t rb2 = (((size_t)bh)<<10) + i0;
  if (t < 64) mrow[t] = ml[rb2 + t];
  for (int f = t; f < 64*NBKT; f += 256) sb[f] = 0.f;
  for (int f = t; f < NBKT*64; f += 256) tvs[f] = tv[f];
  __syncthreads();

  int tx = t & 15, ty = t >> 4;
  float acc[4][4];
  #pragma unroll
  for (int i=0;i<4;i++)
    #pragma unroll
    for(int d=0;d<4;d++) acc[i][d]=0.f;
  const float* vb = qkv_v + ((size_t)(b<<10))*QKVD + (h<<6) + 1024;

  int sr = t >> 2;
  int q0 = (t & 3) << 4;
  int iglob = i0 + sr;
  int syi = iglob >> 5, sxi = iglob & 31;

  for (int jt = 0; jt < 16; jt++){
    int j0 = jt << 6;
    #pragma unroll
    for (int it = 0; it < 4; it++){
      int f = t + (it<<8);
      int r = f >> 4, c4 = (f&15)<<2;
      float4 sv = *(const float4*)(S + (rb2 + r)*NQ + j0 + c4);
      float m = mrow[r];
      ps[r*65+c4+0] = fexp(sv.x - m);
      ps[r*65+c4+1] = fexp(sv.y - m);
      ps[r*65+c4+2] = fexp(sv.z - m);
      ps[r*65+c4+3] = fexp(sv.w - m);
      float4 vv = *(const float4*)(vb + (size_t)(j0+r)*QKVD + c4);
      vs[r*65+c4+0]=vv.x; vs[r*65+c4+1]=vv.y; vs[r*65+c4+2]=vv.z; vs[r*65+c4+3]=vv.w;
    }
    __syncthreads();

    {
      float runv = 0.f; int runb = -1;
      #pragma unroll
      for (int q = 0; q < 16; q++){
        int jj = q0 + q;
        int j = j0 + jj;
        int dy = syi - (j>>5), dx = sxi - (j&31);
        int bkt = ((int)c_pidx[dy+31]+4)*9 + ((int)c_pidx[dx+31]+4);
        float pvv = ps[sr*65 + jj];
        if (bkt == runb) runv += pvv;
        else {
          if (runb >= 0) atomicAdd(&sb[sr*NBKT + runb], runv);
          runb = bkt; runv = pvv;
        }
      }
      atomicAdd(&sb[sr*NBKT + runb], runv);
    }

    #pragma unroll
    for (int k = 0; k < 64; k++){
      float bv[4], a[4];
      #pragma unroll
      for (int dd=0; dd<4; dd++) bv[dd] = vs[k*65 + (tx<<2)+dd];
      #pragma unroll
      for (int ii=0; ii<4; ii++) a[ii] = ps[((ty<<2)+ii)*65 + k];
      #pragma unroll
      for (int ii=0;ii<4;ii++)
        #pragma unroll
        for (int dd=0;dd<4;dd++) acc[ii][dd] += a[ii]*bv[dd];
    }
    __syncthreads();
  }

  if (t < 64){
    float s = 0.f;
    #pragma unroll
    for (int c = 0; c < NBKT; c++) s += sb[t*NBKT + c];
    rsv[t] = 1.0f / s;
  }
  __syncthreads();

  #pragma unroll
  for (int ii=0; ii<4; ii++){
    int r = (ty<<2)+ii;
    float inv = rsv[r];
    float o0=acc[ii][0]*inv, o1=acc[ii][1]*inv, o2=acc[ii][2]*inv, o3=acc[ii][3]*inv;
    for (int c = 0; c < NBKT; c++){
      float svc = sb[r*NBKT + c] * inv;
      float4 tvv = *(const float4*)&tvs[(c<<6) + (tx<<2)];
      o0 = fmaf(svc, tvv.x, o0); o1 = fmaf(svc, tvv.y, o1);
      o2 = fmaf(svc, tvv.z, o2); o3 = fmaf(svc, tvv.w, o3);
    }
    float* op = out + ((size_t)(b<<10) + i0 + r)*CDIM + (h<<6) + (tx<<2);
    *(float4*)op = make_float4(o0,o1,o2,o3);
  }
}

// ---------------- launch ----------------------------------------------------
extern "C" void kernel_launch(void* const* d_in, const int* in_sizes, int n_in,
                              void* d_out, int out_size)
{
  const float* x0     = (const float*)d_in[0];
  const float* x1     = (const float*)d_in[1];
  const float* ln00_g = (const float*)d_in[2];
  const float* ln00_b = (const float*)d_in[3];
  const float* ln01_g = (const float*)d_in[4];
  const float* ln01_b = (const float*)d_in[5];
  const float* ln10_g = (const float*)d_in[6];
  const float* ln10_b = (const float*)d_in[7];
  const float* ln11_g = (const float*)d_in[8];
  const float* ln11_b = (const float*)d_in[9];
  const float* w_qkv0 = (const float*)d_in[10];
  const float* b_qkv0 = (const float*)d_in[11];
  const float* w_qkv1 = (const float*)d_in[12];
  const float* b_qkv1 = (const float*)d_in[13];
  const float* w_proj = (const float*)d_in[14];
  const float* b_proj = (const float*)d_in[15];
  const float* table_q= (const float*)d_in[16];
  const float* table_k= (const float*)d_in[17];
  const float* table_v= (const float*)d_in[18];
  const float* w_fc1_0= (const float*)d_in[19];
  const float* b_fc1_0= (const float*)d_in[20];
  const float* w_fc2_0= (const float*)d_in[21];
  const float* b_fc2_0= (const float*)d_in[22];
  const float* w_fc1_1= (const float*)d_in[23];
  const float* b_fc1_1= (const float*)d_in[24];
  const float* w_fc2_1= (const float*)d_in[25];
  const float* b_fc2_1= (const float*)d_in[26];

  float* out0 = (float*)d_out;
  float* out1 = (float*)d_out + (size_t)ROWS*CDIM;

  float *ln0, *ln1, *qkv0, *qkv1, *att0, *att1, *lk0, *lk1, *lq0, *lq1;
  float *lg0, *lg1, *ml0, *ml1, *hid0, *hid1;
  cudaGetSymbolAddress((void**)&ln0,  g_ln);     ln1  = ln0  + (size_t)ROWS*CDIM;
  cudaGetSymbolAddress((void**)&qkv0, g_qkv);    qkv1 = qkv0 + (size_t)ROWS*QKVD;
  cudaGetSymbolAddress((void**)&att0, g_att);    att1 = att0 + (size_t)ROWS*CDIM;
  cudaGetSymbolAddress((void**)&lk0,  g_lk);     lk1  = lk0  + (size_t)BHN*NBKT;
  cudaGetSymbolAddress((void**)&lq0,  g_lq);     lq1  = lq0  + (size_t)BHN*NBKT;
  cudaGetSymbolAddress((void**)&lg0,  g_logits); lg1  = lg0  + (size_t)32*NQ*NQ;
  cudaGetSymbolAddress((void**)&ml0,  g_ml);     ml1  = ml0  + (size_t)BHN;
  cudaGetSymbolAddress((void**)&hid0, g_hid);    hid1 = hid0 + (size_t)ROWS*HID;

  const int LOGITS_SMEM = 18688 * 4;
  const int PV_SMEM     = 18816 * 4;
  static int attr_done = 0;
  if (!attr_done){
    cudaFuncSetAttribute(logits_kernel, cudaFuncAttributeMaxDynamicSharedMemorySize, LOGITS_SMEM);
    cudaFuncSetAttribute(pv_kernel,     cudaFuncAttributeMaxDynamicSharedMemorySize, PV_SMEM);
    attr_done = 1;
  }

  // 1. LN for qkv inputs
  ln_kernel<<<ROWS, 128>>>(x0, ln00_g, ln00_b, ln0);
  ln_kernel<<<ROWS, 128>>>(x1, ln01_g, ln01_b, ln1);

  // 2. qkv GEMMs (tf32 tensor cores)
  dim3 gqkv(QKVD/128, ROWS/128);
  sgemm_tf32_kernel<<<gqkv, 256>>>(ln0, w_qkv0, b_qkv0, nullptr, qkv0, ROWS, QKVD, CDIM, 0);
  sgemm_tf32_kernel<<<gqkv, 256>>>(ln1, w_qkv1, b_qkv1, nullptr, qkv1, ROWS, QKVD, CDIM, 0);

  // 3. bias tables LK/LQ
  dim3 gbt(BHN/64, 2, 2);
  biastab_kernel<<<gbt, 256>>>(qkv0, qkv1, table_q, table_k, lk0, lk1, lq0, lq1);

  // 4. logits
  dim3 glg(16, 16, 32);
  logits_kernel<<<glg, 256, LOGITS_SMEM>>>(qkv0, qkv1, lk0, lq0, lg0);
  logits_kernel<<<glg, 256, LOGITS_SMEM>>>(qkv1, qkv0, lk1, lq1, lg1);

  // 5. row max
  smax_kernel<<<BHN, 256>>>(lg0, ml0);
  smax_kernel<<<BHN, 256>>>(lg1, ml1);

  // 6. PV + relative-position V table
  dim3 gpv(16, 32);
  pv_kernel<<<gpv, 256, PV_SMEM>>>(lg0, ml0, qkv1, table_v, att0);
  pv_kernel<<<gpv, 256, PV_SMEM>>>(lg1, ml1, qkv0, table_v, att1);

  // 7. proj + residual -> out
  dim3 gproj(CDIM/128, ROWS/128);
  sgemm_tf32_kernel<<<gproj, 256>>>(att0, w_proj, b_proj, x0, out0, ROWS, CDIM, CDIM, 0);
  sgemm_tf32_kernel<<<gproj, 256>>>(att1, w_proj, b_proj, x1, out1, ROWS, CDIM, CDIM, 0);

  // 8. MLP
  ln_kernel<<<ROWS, 128>>>(out0, ln10_g, ln10_b, ln0);
  ln_kernel<<<ROWS, 128>>>(out1, ln11_g, ln11_b, ln1);

  dim3 gfc1(HID/128, ROWS/128);
  sgemm_tf32_kernel<<<gfc1, 256>>>(ln0, w_fc1_0, b_fc1_0, nullptr, hid0, ROWS, HID, CDIM, 1);
  sgemm_tf32_kernel<<<gfc1, 256>>>(ln1, w_fc1_1, b_fc1_1, nullptr, hid1, ROWS, HID, CDIM, 1);

  dim3 gfc2(CDIM/128, ROWS/128);
  sgemm_tf32_kernel<<<gfc2, 256>>>(hid0, w_fc2_0, b_fc2_0, out0, out0, ROWS, CDIM, HID, 0);
  sgemm_tf32_kernel<<<gfc2, 256>>>(hid1, w_fc2_1, b_fc2_1, out1, out1, ROWS, CDIM, HID, 0);
}